// round 10
// baseline (speedup 1.0000x reference)
#include <cuda_runtime.h>
#include <cuda_fp16.h>
#include <cstdint>

// ---------------- problem constants ----------------
#define Bn   8
#define Sn   512
#define Ln   6
#define Dn   512
#define Hn   8
#define HDn  64
#define HIDn 2048
#define Cn   256
#define INDIM 257
#define Mn   (Bn * Sn)          // 4096 rows

#define OUT_LOGITS_PER_B 1020   // 2 * 510
#define OUT_FEAS_OFF     (Bn * OUT_LOGITS_PER_B)   // 8160

// ---------------- scratch (device globals; no allocation) ----------------
__device__ float  g_x  [Mn * Dn];            // residual stream (fp32)
__device__ __half g_xt [Mn * Dn];            // residual stream (fp16)
__device__ __half g_q  [Mn * Dn];            // Q (fp16)
__device__ __half g_k  [Mn * Dn];            // K (fp16)
__device__ __half g_att[Mn * Dn];            // attention out (fp16)
__device__ __half g_vT [Mn * Dn];            // V^T per head [b,h,e,s] (fp16)
__device__ __half g_h  [Mn * HIDn];          // FFN hidden (fp16)
// transposed weights ([N,K] K-major, fp16)
__device__ __half g_wqkvT[Ln * 1536 * Dn];   // concat QKV [1536,512] per layer
__device__ float  g_bqkv [Ln * 1536];
__device__ __half g_woT[Ln * Dn * Dn];
__device__ __half g_w1T[Ln * Dn * HIDn];
__device__ __half g_w2T[Ln * HIDn * Dn];

// ============================================================
// portable PTX helpers
// ============================================================
__device__ __forceinline__ uint32_t su32(const void* p) {
    uint32_t a;
    asm("{ .reg .u64 t; cvta.to.shared.u64 t, %1; cvt.u32.u64 %0, t; }" : "=r"(a) : "l"(p));
    return a;
}
__device__ __forceinline__ void cp_async16(uint32_t s, const void* g) {
    asm volatile("cp.async.cg.shared.global [%0], [%1], 16;" :: "r"(s), "l"(g));
}
#define CP_COMMIT() asm volatile("cp.async.commit_group;" ::: "memory")
#define CP_WAIT(n)  asm volatile("cp.async.wait_group %0;" :: "n"(n) : "memory")

// fp16 mma: D(f32) += A(f16) B(f16)^T ; A=4 regs (8 halves), B=2 regs (4 halves)
#define MMA16(dd, af, b0, b1) \
    asm volatile("mma.sync.aligned.m16n8k16.row.col.f32.f16.f16.f32 " \
        "{%0,%1,%2,%3}, {%4,%5,%6,%7}, {%8,%9}, {%0,%1,%2,%3};" \
        : "+f"((dd)[0]), "+f"((dd)[1]), "+f"((dd)[2]), "+f"((dd)[3]) \
        : "r"((af)[0]), "r"((af)[1]), "r"((af)[2]), "r"((af)[3]), "r"(b0), "r"(b1))

// ldmatrix x4: each lane supplies the address of one 16B row of an 8x8 b16 tile
#define LDSM4(r0, r1, r2, r3, addr) \
    asm volatile("ldmatrix.sync.aligned.m8n8.x4.shared.b16 {%0,%1,%2,%3}, [%4];" \
        : "=r"(r0), "=r"(r1), "=r"(r2), "=r"(r3) : "r"(addr))

// half-element index in a [row][64-half] tile (128B rows, 16B-chunk XOR swizzle)
__device__ __forceinline__ int swzh(int row, int k) {
    return (row << 6) + ((((k >> 3) ^ row) & 7) << 3) + (k & 7);
}
__device__ __forceinline__ uint32_t ldsu(const __half* p) {
    return *(const uint32_t*)p;
}

// ============================================================
// fp16 mma.sync GEMM: C = scale*(A B^T) (+bias, +Res, ReLU)
// CTA 128 x (NT*16); BK=64 halves; 3-stage cp.async; 128 threads; 2 CTAs/SM.
// ldmatrix.x4 fragment loads. QKV: epilogue routes q/k/vT (fp16).
// TOUT: C is fp16. Ct: fp16 shadow of C.
// ============================================================
template<int NT, bool RELU, bool RES, bool QKV, bool TOUT>
__global__ __launch_bounds__(128, 2) void mma_gemm(
    const __half* __restrict__ A, int lda,
    const __half* __restrict__ B, int ldb,
    void* __restrict__ Cp, int ldc,
    const float* __restrict__ bias, const float* __restrict__ Res,
    float scale, int K,
    __half* __restrict__ Ck, __half* __restrict__ Cv, __half* __restrict__ Ct)
{
    constexpr int BM = 128, BK = 64;
    constexpr int BN = NT * 16;
    constexpr int NSTAGE = 3;
    constexpr int STAGE_H = (BM + BN) * BK;      // halves per stage

    extern __shared__ float smem[];
    float* sbias = smem;
    __half* sdata = (__half*)(smem + BN);

    const int t = threadIdx.x;
    const int m0 = blockIdx.y * BM;
    const int n0 = blockIdx.x * BN;

    if (bias != nullptr && t < BN) sbias[t] = bias[n0 + t];

    auto load_stage = [&](int st, int k0) {
        __half* sa = sdata + (st % NSTAGE) * STAGE_H;
        __half* sb = sa + BM * BK;
        #pragma unroll
        for (int i = 0; i < 8; i++) {             // A: 128 rows x 8 chunks
            int j = t + 128 * i;
            int m = j >> 3, f = j & 7;
            uint32_t dst = su32(&sa[(m << 6) + (((f ^ m) & 7) << 3)]);
            cp_async16(dst, A + (size_t)(m0 + m) * lda + k0 + (f << 3));
        }
        #pragma unroll
        for (int i = 0; i < NT; i++) {            // B: BN rows x 8 chunks
            int j = t + 128 * i;
            int n = j >> 3, f = j & 7;
            uint32_t dst = su32(&sb[(n << 6) + (((f ^ n) & 7) << 3)]);
            cp_async16(dst, B + (size_t)(n0 + n) * ldb + k0 + (f << 3));
        }
        CP_COMMIT();
    };

    const int nst = K / BK;
    load_stage(0, 0);
    load_stage(1, BK);

    const int lane = t & 31, w = t >> 5;
    const int wm = w >> 1, wn = w & 1;
    const int g = lane >> 2, t4 = lane & 3;
    // ldmatrix lane->address constants
    const int jj  = lane >> 3;                   // 0..3 (matrix id)
    const int rA  = ((jj & 1) << 3) + (lane & 7);
    const int kA  = (jj >> 1) << 3;
    const int rB  = lane & 7;
    const int ntO = jj >> 1;                     // which nt of the pair
    const int kB_ = (jj & 1) << 3;

    float d[4][NT][4] = {};

    for (int s = 0; s < nst; s++) {
        if (s < nst - 1) { CP_WAIT(1); } else { CP_WAIT(0); }
        __syncthreads();
        if (s + 2 < nst) load_stage(s + 2, (s + 2) * BK);

        uint32_t sa_u = su32(sdata + (s % NSTAGE) * STAGE_H);
        uint32_t sb_u = sa_u + BM * BK * 2;
        #pragma unroll
        for (int k16 = 0; k16 < 4; k16++) {
            const int kb = k16 << 4;
            uint32_t af[4][4];
            #pragma unroll
            for (int mt = 0; mt < 4; mt++) {
                int r = wm * 64 + mt * 16 + rA;
                LDSM4(af[mt][0], af[mt][1], af[mt][2], af[mt][3],
                      sa_u + (swzh(r, kb + kA) << 1));
            }
            uint32_t bf[NT][2];
            #pragma unroll
            for (int np = 0; np < NT / 2; np++) {
                int n = wn * NT * 8 + ((np * 2 + ntO) << 3) + rB;
                LDSM4(bf[np * 2][0], bf[np * 2][1], bf[np * 2 + 1][0], bf[np * 2 + 1][1],
                      sb_u + (swzh(n, kb + kB_) << 1));
            }
            #pragma unroll
            for (int nt = 0; nt < NT; nt++)
                #pragma unroll
                for (int mt = 0; mt < 4; mt++) MMA16(d[mt][nt], af[mt], bf[nt][0], bf[nt][1]);
        }
    }

    // ---------------- epilogue ----------------
    const int colw = wn * NT * 8;
    #pragma unroll
    for (int mt = 0; mt < 4; mt++) {
        #pragma unroll
        for (int h2 = 0; h2 < 2; h2++) {
            const int m = m0 + wm * 64 + mt * 16 + g + h2 * 8;
            if (QKV) {
                const int region = n0 >> 9;       // 0=Q, 1=K, 2=V
                const int nb = n0 & 511;
                if (region < 2) {
                    __half* crow = (region == 0 ? (__half*)Cp : Ck) + (size_t)m * 512 + nb;
                    #pragma unroll
                    for (int nt = 0; nt < NT; nt++) {
                        int cl = colw + nt * 8 + 2 * t4;
                        float v0 = d[mt][nt][h2 * 2]     + sbias[cl];
                        float v1 = d[mt][nt][h2 * 2 + 1] + sbias[cl + 1];
                        *(__half2*)(crow + cl) = __floats2half2_rn(v0, v1);
                    }
                } else {
                    #pragma unroll
                    for (int nt = 0; nt < NT; nt++) {
                        int cl = colw + nt * 8 + 2 * t4;
                        float v0 = d[mt][nt][h2 * 2]     + sbias[cl];
                        float v1 = d[mt][nt][h2 * 2 + 1] + sbias[cl + 1];
                        int gc = nb + cl;
                        int hh = gc >> 6, e = gc & 63;
                        size_t base = ((size_t)((m >> 9) * Hn + hh) * 64 + e) * 512
                                      + (size_t)(m & 511);
                        Cv[base]       = __float2half_rn(v0);
                        Cv[base + 512] = __float2half_rn(v1);
                    }
                }
            } else if (TOUT) {
                __half* crow = (__half*)Cp + (size_t)m * ldc + n0;
                #pragma unroll
                for (int nt = 0; nt < NT; nt++) {
                    int cl = colw + nt * 8 + 2 * t4;
                    float v0 = d[mt][nt][h2 * 2]     + sbias[cl];
                    float v1 = d[mt][nt][h2 * 2 + 1] + sbias[cl + 1];
                    if (RELU) { v0 = fmaxf(v0, 0.f); v1 = fmaxf(v1, 0.f); }
                    *(__half2*)(crow + cl) = __floats2half2_rn(v0, v1);
                }
            } else {
                float* crow = (float*)Cp + (size_t)m * ldc + n0;
                __half* trow = (Ct != nullptr) ? (Ct + (size_t)m * ldc + n0) : nullptr;
                const float* rrow = RES ? (Res + (size_t)m * ldc + n0) : nullptr;
                #pragma unroll
                for (int nt = 0; nt < NT; nt++) {
                    int cl = colw + nt * 8 + 2 * t4;
                    float v0 = d[mt][nt][h2 * 2]     * scale;
                    float v1 = d[mt][nt][h2 * 2 + 1] * scale;
                    if (bias != nullptr) { v0 += sbias[cl]; v1 += sbias[cl + 1]; }
                    if (RELU) { v0 = fmaxf(v0, 0.f); v1 = fmaxf(v1, 0.f); }
                    if (RES) {
                        float2 r = *(const float2*)(rrow + cl);
                        v0 += r.x; v1 += r.y;
                    }
                    *(float2*)(crow + cl) = make_float2(v0, v1);
                    if (Ct != nullptr)
                        *(__half2*)(trow + cl) = __floats2half2_rn(v0, v1);
                }
            }
        }
    }
}

// ============================================================
// flash attention (fp16 operands, fp32 accum/softmax), ldmatrix frag loads
// per (b,h,qtile 128); 256 threads; smem 96KB.
// ============================================================
#define FLASH_SMEM 98304
#define NEG_INF (-1e30f)

__global__ __launch_bounds__(256) void flash_kernel()
{
    extern __shared__ __half smh[];
    __half* Ps = smh;                          // 16384 halves

    const int t = threadIdx.x;
    const int lane = t & 31, w = t >> 5;
    const int g = lane >> 2, t4 = lane & 3;
    const int jj  = lane >> 3;
    const int rA  = ((jj & 1) << 3) + (lane & 7);
    const int kA  = (jj >> 1) << 3;
    const int rB  = lane & 7;
    const int ntO = jj >> 1;
    const int kB_ = (jj & 1) << 3;
    const int q0 = blockIdx.x * 128;
    const int b = blockIdx.y >> 3, h = blockIdx.y & 7;
    const int r0 = w * 16;

    const __half* qg = g_q  + (size_t)(b * Sn + q0) * Dn + h * HDn;
    const __half* kg = g_k  + (size_t)(b * Sn) * Dn + h * HDn;
    const __half* vg = g_vT + (size_t)(b * Hn + h) * HDn * Sn;

    // ---- stage Q into Ps chunk0: [128 q][64 e] ----
    #pragma unroll
    for (int i = 0; i < 4; i++) {
        int j = t + 256 * i;
        int r = j >> 3, f = j & 7;
        uint32_t dst = su32(&Ps[(r << 6) + (((f ^ r) & 7) << 3)]);
        cp_async16(dst, qg + (size_t)r * Dn + (f << 3));
    }
    CP_COMMIT();

    auto load_kv = [&](int tile, int st) {
        __half* kb = smh + 16384 + st * 16384;
        __half* vb = kb + 8192;
        #pragma unroll
        for (int i = 0; i < 4; i++) {          // K tile [128 s][64 e]
            int j = t + 256 * i;
            int r = j >> 3, f = j & 7;
            uint32_t dst = su32(&kb[(r << 6) + (((f ^ r) & 7) << 3)]);
            cp_async16(dst, kg + (size_t)(tile * 128 + r) * Dn + (f << 3));
        }
        #pragma unroll
        for (int i = 0; i < 4; i++) {          // V^T tile [64 e][128 s] -> 2 chunks
            int j = t + 256 * i;
            int e = j >> 4, f = j & 15;
            int ss = f >> 3, fc = f & 7;
            uint32_t dst = su32(&vb[ss * 4096 + (e << 6) + (((fc ^ e) & 7) << 3)]);
            cp_async16(dst, vg + (size_t)e * Sn + tile * 128 + (f << 3));
        }
        CP_COMMIT();
    };
    load_kv(0, 0);
    load_kv(1, 1);

    // ---- Q fragments (held in regs) ----
    CP_WAIT(2);
    __syncthreads();
    uint32_t qf[4][4];
    {
        uint32_t ps_u = su32(Ps);
        #pragma unroll
        for (int k16 = 0; k16 < 4; k16++) {
            const int kb = k16 << 4;
            LDSM4(qf[k16][0], qf[k16][1], qf[k16][2], qf[k16][3],
                  ps_u + (swzh(r0 + rA, kb + kA) << 1));
        }
    }
    __syncthreads();

    float m0 = NEG_INF, m1 = NEG_INF, l0 = 0.f, l1 = 0.f;
    float o[8][4] = {};
    const uint32_t ps_u = su32(Ps);

    for (int tile = 0; tile < 4; tile++) {
        if (tile < 3) { CP_WAIT(1); } else { CP_WAIT(0); }
        __syncthreads();
        const __half* kbp = smh + 16384 + (tile & 1) * 16384;
        const uint32_t kb_u = su32(kbp);
        const uint32_t vb_u = kb_u + 8192 * 2;

        // ---- S = Q K^T ----
        float s[16][4];
        #pragma unroll
        for (int nt = 0; nt < 16; nt++)
            #pragma unroll
            for (int j = 0; j < 4; j++) s[nt][j] = 0.f;
        #pragma unroll
        for (int k16 = 0; k16 < 4; k16++) {
            const int kk = k16 << 4;
            #pragma unroll
            for (int np = 0; np < 8; np++) {
                uint32_t b00, b01, b10, b11;
                int n = ((np * 2 + ntO) << 3) + rB;
                LDSM4(b00, b01, b10, b11, kb_u + (swzh(n, kk + kB_) << 1));
                MMA16(s[np * 2],     qf[k16], b00, b01);
                MMA16(s[np * 2 + 1], qf[k16], b10, b11);
            }
        }

        // ---- online softmax update ----
        float rm0 = NEG_INF, rm1 = NEG_INF;
        #pragma unroll
        for (int nt = 0; nt < 16; nt++) {
            s[nt][0] *= 0.125f; s[nt][1] *= 0.125f;
            s[nt][2] *= 0.125f; s[nt][3] *= 0.125f;
            rm0 = fmaxf(rm0, fmaxf(s[nt][0], s[nt][1]));
            rm1 = fmaxf(rm1, fmaxf(s[nt][2], s[nt][3]));
        }
        rm0 = fmaxf(rm0, __shfl_xor_sync(0xFFFFFFFF, rm0, 1));
        rm0 = fmaxf(rm0, __shfl_xor_sync(0xFFFFFFFF, rm0, 2));
        rm1 = fmaxf(rm1, __shfl_xor_sync(0xFFFFFFFF, rm1, 1));
        rm1 = fmaxf(rm1, __shfl_xor_sync(0xFFFFFFFF, rm1, 2));
        float mn0 = fmaxf(m0, rm0), mn1 = fmaxf(m1, rm1);
        float a0 = __expf(m0 - mn0), a1 = __expf(m1 - mn1);
        m0 = mn0; m1 = mn1;

        float rs0 = 0.f, rs1 = 0.f;
        #pragma unroll
        for (int nt = 0; nt < 16; nt++) {
            float p0 = __expf(s[nt][0] - m0);
            float p1 = __expf(s[nt][1] - m0);
            float p2 = __expf(s[nt][2] - m1);
            float p3 = __expf(s[nt][3] - m1);
            rs0 += p0 + p1; rs1 += p2 + p3;
            int col = nt * 8 + 2 * t4;
            int ch = col >> 6, kc = col & 63;
            *(__half2*)&Ps[ch * 8192 + swzh(r0 + g, kc)]     = __floats2half2_rn(p0, p1);
            *(__half2*)&Ps[ch * 8192 + swzh(r0 + g + 8, kc)] = __floats2half2_rn(p2, p3);
        }
        rs0 += __shfl_xor_sync(0xFFFFFFFF, rs0, 1);
        rs0 += __shfl_xor_sync(0xFFFFFFFF, rs0, 2);
        rs1 += __shfl_xor_sync(0xFFFFFFFF, rs1, 1);
        rs1 += __shfl_xor_sync(0xFFFFFFFF, rs1, 2);
        l0 = l0 * a0 + rs0;
        l1 = l1 * a1 + rs1;
        #pragma unroll
        for (int nt = 0; nt < 8; nt++) {
            o[nt][0] *= a0; o[nt][1] *= a0;
            o[nt][2] *= a1; o[nt][3] *= a1;
        }
        __syncwarp();

        // ---- O += P @ V^T ----
        #pragma unroll
        for (int ks = 0; ks < 8; ks++) {
            const int ch = ks >> 2, kk = (ks << 4) & 63;
            uint32_t af[4];
            LDSM4(af[0], af[1], af[2], af[3],
                  ps_u + ch * 16384 + (swzh(r0 + rA, kk + kA) << 1));
            #pragma unroll
            for (int np = 0; np < 4; np++) {
                uint32_t b00, b01, b10, b11;
                int n = ((np * 2 + ntO) << 3) + rB;
                LDSM4(b00, b01, b10, b11, vb_u + ch * 8192 + (swzh(n, kk + kB_) << 1));
                MMA16(o[np * 2],     af, b00, b01);
                MMA16(o[np * 2 + 1], af, b10, b11);
            }
        }
        __syncthreads();
        if (tile + 2 < 4) load_kv(tile + 2, tile & 1);
    }

    // ---- epilogue: O / l -> g_att (fp16) ----
    float inv0 = 1.0f / l0, inv1 = 1.0f / l1;
    __half* orow0 = g_att + (size_t)(b * Sn + q0 + r0 + g) * Dn + h * HDn;
    __half* orow1 = orow0 + 8 * Dn;
    #pragma unroll
    for (int nt = 0; nt < 8; nt++) {
        int col = nt * 8 + 2 * t4;
        *(__half2*)(orow0 + col) = __floats2half2_rn(o[nt][0] * inv0, o[nt][1] * inv0);
        *(__half2*)(orow1 + col) = __floats2half2_rn(o[nt][2] * inv1, o[nt][3] * inv1);
    }
}

// ============================================================
// weight transpose -> fp16: dst[zdst + c*R + r] = h(src[z][r][c])
// ============================================================
__global__ void transpose_kernel(const float* __restrict__ src, __half* __restrict__ dst,
                                 int R, int C, size_t zstride, size_t doff)
{
    __shared__ float tile[32][33];
    size_t zsrc = (size_t)blockIdx.z * R * C;
    size_t zdst = (size_t)blockIdx.z * zstride + doff;
    int c0 = blockIdx.x * 32, r0 = blockIdx.y * 32;
    int tx = threadIdx.x, ty = threadIdx.y;       // 32 x 8
    #pragma unroll
    for (int j = 0; j < 32; j += 8)
        tile[ty + j][tx] = src[zsrc + (size_t)(r0 + ty + j) * C + c0 + tx];
    __syncthreads();
    #pragma unroll
    for (int j = 0; j < 32; j += 8)
        dst[zdst + (size_t)(c0 + ty + j) * R + r0 + tx] = __float2half_rn(tile[tx][ty + j]);
}

__global__ void packbias_kernel(const float* __restrict__ bq, const float* __restrict__ bk,
                                const float* __restrict__ bv, float* __restrict__ dst)
{
    int i = blockIdx.x, t = threadIdx.x;   // Ln x 512
    dst[i * 1536 + t]        = bq[i * 512 + t];
    dst[i * 1536 + 512 + t]  = bk[i * 512 + t];
    dst[i * 1536 + 1024 + t] = bv[i * 512 + t];
}

// ============================================================
// build x = class_proj(concat(embed[idx], nd)); writes fp32 + fp16 shadow
// ============================================================
__global__ void build_x_kernel(const float* __restrict__ sol,
                               const float* __restrict__ cap,
                               const float* __restrict__ emb,
                               const float* __restrict__ srcW, const float* __restrict__ srcB,
                               const float* __restrict__ candW, const float* __restrict__ candB,
                               const float* __restrict__ depW, const float* __restrict__ depB)
{
    int row = blockIdx.x;
    int b = row / Sn, s = row % Sn;
    __shared__ float xin[INDIM];
    int t = threadIdx.x;

    int idx = (int)sol[(size_t)row * 4 + 0];
    xin[t] = emb[(size_t)idx * Cn + t];
    if (t == 0) {
        float rem = sol[(size_t)(b * Sn) * 4 + 3];
        float nd = (s == 0) ? 0.0f : 2.0f * (sol[(size_t)row * 4 + 2] - rem) / cap[b];
        xin[Cn] = nd;
    }
    __syncthreads();

    const float* W; const float* bb;
    if (s == 0)           { W = srcW;  bb = srcB;  }
    else if (s == Sn - 1) { W = depW;  bb = depB;  }
    else                  { W = candW; bb = candB; }

    int c = t;
    float acc0 = bb[c], acc1 = bb[c + 256];
    #pragma unroll 4
    for (int k = 0; k < INDIM; k++) {
        float xv = xin[k];
        acc0 += xv * W[k * Dn + c];
        acc1 += xv * W[k * Dn + c + 256];
    }
    g_x [(size_t)row * Dn + c]       = acc0;
    g_x [(size_t)row * Dn + c + 256] = acc1;
    g_xt[(size_t)row * Dn + c]       = __float2half_rn(acc0);
    g_xt[(size_t)row * Dn + c + 256] = __float2half_rn(acc1);
}

// ============================================================
// feasibility head
// ============================================================
__global__ void feas_kernel(const float* __restrict__ fW,
                            const float* __restrict__ fB,
                            float* __restrict__ out)
{
    int s = blockIdx.x + 1;
    int b = blockIdx.y;
    const float* xr = g_x + (size_t)(b * Sn + s) * Dn;
    int t = threadIdx.x;
    float acc = 0.f;
    #pragma unroll 4
    for (int k = t; k < Dn; k += 128) acc += xr[k] * fW[k];
    __shared__ float red[128];
    red[t] = acc; __syncthreads();
    for (int o = 64; o > 0; o >>= 1) {
        if (t < o) red[t] += red[t + o];
        __syncthreads();
    }
    if (t == 0) out[OUT_FEAS_OFF + b * 510 + (s - 1)] = red[0] + fB[0];
}

// ============================================================
// pointer logits
// ============================================================
__global__ void logits_kernel(const float* __restrict__ pW,
                              const float* __restrict__ pB,
                              float* __restrict__ out)
{
    int s = blockIdx.x + 1;
    int b = blockIdx.y;
    const float* xr = g_x + (size_t)(b * Sn + s) * Dn;
    int t = threadIdx.x;
    float a0 = 0.f, a1 = 0.f;
    #pragma unroll 4
    for (int k = t; k < Dn; k += 128) {
        float xv = xr[k];
        a0 += xv * pW[k * 2 + 0];
        a1 += xv * pW[k * 2 + 1];
    }
    __shared__ float r0[128], r1[128];
    r0[t] = a0; r1[t] = a1; __syncthreads();
    for (int o = 64; o > 0; o >>= 1) {
        if (t < o) { r0[t] += r0[t + o]; r1[t] += r1[t + o]; }
        __syncthreads();
    }
    if (t == 0) {
        out[b * OUT_LOGITS_PER_B + (s - 1)]       = r0[0] + pB[0];
        out[b * OUT_LOGITS_PER_B + 510 + (s - 1)] = r1[0] + pB[1];
    }
}

// ============================================================
// host orchestration
// ============================================================
extern "C" void kernel_launch(void* const* d_in, const int* in_sizes, int n_in,
                              void* d_out, int out_size)
{
    const float* sol   = (const float*)d_in[0];
    const float* cap   = (const float*)d_in[1];
    const float* emb   = (const float*)d_in[2];
    const float* srcW  = (const float*)d_in[3];
    const float* srcB  = (const float*)d_in[4];
    const float* candW = (const float*)d_in[5];
    const float* candB = (const float*)d_in[6];
    const float* depW  = (const float*)d_in[7];
    const float* depB  = (const float*)d_in[8];
    const float* feasW = (const float*)d_in[9];
    const float* feasB = (const float*)d_in[10];
    const float* Wq    = (const float*)d_in[11];
    const float* bq    = (const float*)d_in[12];
    const float* Wk    = (const float*)d_in[13];
    const float* bk    = (const float*)d_in[14];
    const float* Wv    = (const float*)d_in[15];
    const float* bv    = (const float*)d_in[16];
    const float* Wo    = (const float*)d_in[17];
    const float* bo    = (const float*)d_in[18];
    // d_in[19] = s_scale : softmax-shift-invariant, unused
    const float* W1    = (const float*)d_in[20];
    const float* b1    = (const float*)d_in[21];
    const float* W2    = (const float*)d_in[22];
    const float* b2    = (const float*)d_in[23];
    const float* ptrW  = (const float*)d_in[24];
    const float* ptrB  = (const float*)d_in[25];
    float* out = (float*)d_out;
    (void)in_sizes; (void)n_in; (void)out_size;

    float  *px;
    __half *pxt, *pq, *pk, *patt, *pvT, *ph;
    __half *pwqkvT, *pwoT, *pw1T, *pw2T;
    float  *pbqkv;
    cudaGetSymbolAddress((void**)&px,     g_x);
    cudaGetSymbolAddress((void**)&pxt,    g_xt);
    cudaGetSymbolAddress((void**)&pq,     g_q);
    cudaGetSymbolAddress((void**)&pk,     g_k);
    cudaGetSymbolAddress((void**)&patt,   g_att);
    cudaGetSymbolAddress((void**)&pvT,    g_vT);
    cudaGetSymbolAddress((void**)&ph,     g_h);
    cudaGetSymbolAddress((void**)&pwqkvT, g_wqkvT);
    cudaGetSymbolAddress((void**)&pbqkv,  g_bqkv);
    cudaGetSymbolAddress((void**)&pwoT,   g_woT);
    cudaGetSymbolAddress((void**)&pw1T,   g_w1T);
    cudaGetSymbolAddress((void**)&pw2T,   g_w2T);

    const int SM8 = 128 * 4 + 3 * (128 + 128) * 64 * 2;   // 98816
    const int SM4 = 64 * 4 + 3 * (128 + 64) * 64 * 2;     // 73984
    cudaFuncSetAttribute(mma_gemm<8, false, false, true,  false>, cudaFuncAttributeMaxDynamicSharedMemorySize, SM8);
    cudaFuncSetAttribute(mma_gemm<8, true,  false, false, true >, cudaFuncAttributeMaxDynamicSharedMemorySize, SM8);
    cudaFuncSetAttribute(mma_gemm<4, false, true,  false, false>, cudaFuncAttributeMaxDynamicSharedMemorySize, SM4);
    cudaFuncSetAttribute(flash_kernel, cudaFuncAttributeMaxDynamicSharedMemorySize, FLASH_SMEM);

    const size_t DD = (size_t)Dn * Dn;           // 262144
    const size_t DH = (size_t)Dn * HIDn;         // 1048576
    const size_t QKVS = (size_t)1536 * Dn;       // 786432

    // ---- pack weights (fp16): QKV concat [1536,512], others [N,K] ----
    dim3 tb(32, 8);
    transpose_kernel<<<dim3(16, 16, Ln), tb>>>(Wq, pwqkvT, Dn, Dn, QKVS, 0);
    transpose_kernel<<<dim3(16, 16, Ln), tb>>>(Wk, pwqkvT, Dn, Dn, QKVS, DD);
    transpose_kernel<<<dim3(16, 16, Ln), tb>>>(Wv, pwqkvT, Dn, Dn, QKVS, 2 * DD);
    transpose_kernel<<<dim3(16, 16, Ln), tb>>>(Wo, pwoT, Dn, Dn, DD, 0);
    transpose_kernel<<<dim3(64, 16, Ln), tb>>>(W1, pw1T, Dn, HIDn, DH, 0);
    transpose_kernel<<<dim3(16, 64, Ln), tb>>>(W2, pw2T, HIDn, Dn, DH, 0);
    packbias_kernel<<<Ln, 512>>>(bq, bk, bv, pbqkv);

    build_x_kernel<<<Mn, 256>>>(sol, cap, emb, srcW, srcB, candW, candB, depW, depB);

    const dim3 gQKV(12, 32, 1);     // 384 CTAs (BN=128)
    const dim3 gP4 (8, 32, 1);      // 256 CTAs (BN=64)
    const dim3 gFF1(16, 32, 1);     // 512 CTAs
    const dim3 gFl (4, 64, 1);      // 256 CTAs

    for (int i = 0; i < Ln; i++) {
        // ---- fused QKV projection (fp16 outputs; V per-head-transposed) ----
        mma_gemm<8, false, false, true, false><<<gQKV, 128, SM8>>>(
            pxt, Dn,  pwqkvT + i * QKVS, Dn,  pq, Dn,
            pbqkv + i * 1536, nullptr, 1.0f, Dn, pk, pvT, nullptr);

        // ---- flash attention ----
        flash_kernel<<<gFl, 256, FLASH_SMEM>>>();

        // ---- O projection + residual (writes x fp32 + xt fp16) ----
        mma_gemm<4, false, true, false, false><<<gP4, 128, SM4>>>(
            patt, Dn,  pwoT + i * DD, Dn,  px, Dn,
            bo + i * Dn, px, 1.0f, Dn, nullptr, nullptr, pxt);

        if (i == 0)
            feas_kernel<<<dim3(510, Bn), 128>>>(feasW, feasB, out);

        // ---- FFN (h stored fp16) ----
        mma_gemm<8, true, false, false, true><<<gFF1, 128, SM8>>>(
            pxt, Dn,  pw1T + i * DH, Dn,  ph, HIDn,
            b1 + i * HIDn, nullptr, 1.0f, Dn, nullptr, nullptr, nullptr);
        mma_gemm<4, false, true, false, false><<<gP4, 128, SM4>>>(
            ph, HIDn,  pw2T + i * DH, HIDn,  px, Dn,
            b2 + i * Dn, px, 1.0f, HIDn, nullptr, nullptr, pxt);
    }

    logits_kernel<<<dim3(510, Bn), 128>>>(ptrW, ptrB, out);
}

// round 11
// speedup vs baseline: 1.0075x; 1.0075x over previous
#include <cuda_runtime.h>
#include <cuda_fp16.h>
#include <cstdint>

// ---------------- problem constants ----------------
#define Bn   8
#define Sn   512
#define Ln   6
#define Dn   512
#define Hn   8
#define HDn  64
#define HIDn 2048
#define Cn   256
#define INDIM 257
#define Mn   (Bn * Sn)          // 4096 rows

#define OUT_LOGITS_PER_B 1020   // 2 * 510
#define OUT_FEAS_OFF     (Bn * OUT_LOGITS_PER_B)   // 8160

// ---------------- scratch (device globals; no allocation) ----------------
__device__ float  g_x  [Mn * Dn];            // residual stream (fp32)
__device__ __half g_xt [Mn * Dn];            // residual stream (fp16)
__device__ __half g_q  [Mn * Dn];            // Q (fp16)
__device__ __half g_k  [Mn * Dn];            // K (fp16)
__device__ __half g_att[Mn * Dn];            // attention out (fp16)
__device__ __half g_vT [Mn * Dn];            // V^T per head [b,h,e,s] (fp16)
__device__ __half g_h  [Mn * HIDn];          // FFN hidden (fp16)
// transposed weights ([N,K] K-major, fp16)
__device__ __half g_wqkvT[Ln * 1536 * Dn];   // concat QKV [1536,512] per layer
__device__ float  g_bqkv [Ln * 1536];
__device__ __half g_woT[Ln * Dn * Dn];
__device__ __half g_w1T[Ln * Dn * HIDn];
__device__ __half g_w2T[Ln * HIDn * Dn];

// ============================================================
// portable PTX helpers
// ============================================================
__device__ __forceinline__ uint32_t su32(const void* p) {
    uint32_t a;
    asm("{ .reg .u64 t; cvta.to.shared.u64 t, %1; cvt.u32.u64 %0, t; }" : "=r"(a) : "l"(p));
    return a;
}
__device__ __forceinline__ void cp_async16(uint32_t s, const void* g) {
    asm volatile("cp.async.cg.shared.global [%0], [%1], 16;" :: "r"(s), "l"(g));
}
#define CP_COMMIT() asm volatile("cp.async.commit_group;" ::: "memory")
#define CP_WAIT(n)  asm volatile("cp.async.wait_group %0;" :: "n"(n) : "memory")

// fp16 mma: D(f32) += A(f16) B(f16)^T ; A=4 regs (8 halves), B=2 regs (4 halves)
#define MMA16(dd, af, b0, b1) \
    asm volatile("mma.sync.aligned.m16n8k16.row.col.f32.f16.f16.f32 " \
        "{%0,%1,%2,%3}, {%4,%5,%6,%7}, {%8,%9}, {%0,%1,%2,%3};" \
        : "+f"((dd)[0]), "+f"((dd)[1]), "+f"((dd)[2]), "+f"((dd)[3]) \
        : "r"((af)[0]), "r"((af)[1]), "r"((af)[2]), "r"((af)[3]), "r"(b0), "r"(b1))

// ldmatrix x4: each lane supplies the address of one 16B row of an 8x8 b16 tile
#define LDSM4(r0, r1, r2, r3, addr) \
    asm volatile("ldmatrix.sync.aligned.m8n8.x4.shared.b16 {%0,%1,%2,%3}, [%4];" \
        : "=r"(r0), "=r"(r1), "=r"(r2), "=r"(r3) : "r"(addr))

// half-element index in a [row][64-half] tile (128B rows, 16B-chunk XOR swizzle)
__device__ __forceinline__ int swzh(int row, int k) {
    return (row << 6) + ((((k >> 3) ^ row) & 7) << 3) + (k & 7);
}
__device__ __forceinline__ uint32_t ldsu(const __half* p) {
    return *(const uint32_t*)p;
}

// ============================================================
// fp16 mma.sync GEMM: C = scale*(A B^T) (+bias, +Res, ReLU)
// CTA 128 x (NT*16); BK=64 halves; 3-stage cp.async; 128 threads; 2 CTAs/SM.
// ldmatrix.x4 fragment loads. QKV: epilogue routes q/k/vT (fp16).
// TOUT: C is fp16. Ct: fp16 shadow of C.
// ============================================================
template<int NT, bool RELU, bool RES, bool QKV, bool TOUT>
__global__ __launch_bounds__(128, 2) void mma_gemm(
    const __half* __restrict__ A, int lda,
    const __half* __restrict__ B, int ldb,
    void* __restrict__ Cp, int ldc,
    const float* __restrict__ bias, const float* __restrict__ Res,
    float scale, int K,
    __half* __restrict__ Ck, __half* __restrict__ Cv, __half* __restrict__ Ct)
{
    constexpr int BM = 128, BK = 64;
    constexpr int BN = NT * 16;
    constexpr int NSTAGE = 3;
    constexpr int STAGE_H = (BM + BN) * BK;      // halves per stage

    extern __shared__ float smem[];
    float* sbias = smem;
    __half* sdata = (__half*)(smem + BN);

    const int t = threadIdx.x;
    const int m0 = blockIdx.y * BM;
    const int n0 = blockIdx.x * BN;

    if (bias != nullptr && t < BN) sbias[t] = bias[n0 + t];

    auto load_stage = [&](int st, int k0) {
        __half* sa = sdata + (st % NSTAGE) * STAGE_H;
        __half* sb = sa + BM * BK;
        #pragma unroll
        for (int i = 0; i < 8; i++) {             // A: 128 rows x 8 chunks
            int j = t + 128 * i;
            int m = j >> 3, f = j & 7;
            uint32_t dst = su32(&sa[(m << 6) + (((f ^ m) & 7) << 3)]);
            cp_async16(dst, A + (size_t)(m0 + m) * lda + k0 + (f << 3));
        }
        #pragma unroll
        for (int i = 0; i < NT; i++) {            // B: BN rows x 8 chunks
            int j = t + 128 * i;
            int n = j >> 3, f = j & 7;
            uint32_t dst = su32(&sb[(n << 6) + (((f ^ n) & 7) << 3)]);
            cp_async16(dst, B + (size_t)(n0 + n) * ldb + k0 + (f << 3));
        }
        CP_COMMIT();
    };

    const int nst = K / BK;
    load_stage(0, 0);
    load_stage(1, BK);

    const int lane = t & 31, w = t >> 5;
    const int wm = w >> 1, wn = w & 1;
    const int g = lane >> 2, t4 = lane & 3;
    // ldmatrix lane->address constants
    const int jj  = lane >> 3;                   // 0..3 (matrix id)
    const int rA  = ((jj & 1) << 3) + (lane & 7);
    const int kA  = (jj >> 1) << 3;
    const int rB  = lane & 7;
    const int ntO = jj >> 1;                     // which nt of the pair
    const int kB_ = (jj & 1) << 3;

    float d[4][NT][4] = {};

    for (int s = 0; s < nst; s++) {
        if (s < nst - 1) { CP_WAIT(1); } else { CP_WAIT(0); }
        __syncthreads();
        if (s + 2 < nst) load_stage(s + 2, (s + 2) * BK);

        uint32_t sa_u = su32(sdata + (s % NSTAGE) * STAGE_H);
        uint32_t sb_u = sa_u + BM * BK * 2;
        #pragma unroll
        for (int k16 = 0; k16 < 4; k16++) {
            const int kb = k16 << 4;
            uint32_t af[4][4];
            #pragma unroll
            for (int mt = 0; mt < 4; mt++) {
                int r = wm * 64 + mt * 16 + rA;
                LDSM4(af[mt][0], af[mt][1], af[mt][2], af[mt][3],
                      sa_u + (swzh(r, kb + kA) << 1));
            }
            uint32_t bf[NT][2];
            #pragma unroll
            for (int np = 0; np < NT / 2; np++) {
                int n = wn * NT * 8 + ((np * 2 + ntO) << 3) + rB;
                LDSM4(bf[np * 2][0], bf[np * 2][1], bf[np * 2 + 1][0], bf[np * 2 + 1][1],
                      sb_u + (swzh(n, kb + kB_) << 1));
            }
            #pragma unroll
            for (int nt = 0; nt < NT; nt++)
                #pragma unroll
                for (int mt = 0; mt < 4; mt++) MMA16(d[mt][nt], af[mt], bf[nt][0], bf[nt][1]);
        }
    }

    // ---------------- epilogue ----------------
    const int colw = wn * NT * 8;
    #pragma unroll
    for (int mt = 0; mt < 4; mt++) {
        #pragma unroll
        for (int h2 = 0; h2 < 2; h2++) {
            const int m = m0 + wm * 64 + mt * 16 + g + h2 * 8;
            if (QKV) {
                const int region = n0 >> 9;       // 0=Q, 1=K, 2=V
                const int nb = n0 & 511;
                if (region < 2) {
                    __half* crow = (region == 0 ? (__half*)Cp : Ck) + (size_t)m * 512 + nb;
                    #pragma unroll
                    for (int nt = 0; nt < NT; nt++) {
                        int cl = colw + nt * 8 + 2 * t4;
                        float v0 = d[mt][nt][h2 * 2]     + sbias[cl];
                        float v1 = d[mt][nt][h2 * 2 + 1] + sbias[cl + 1];
                        *(__half2*)(crow + cl) = __floats2half2_rn(v0, v1);
                    }
                } else {
                    #pragma unroll
                    for (int nt = 0; nt < NT; nt++) {
                        int cl = colw + nt * 8 + 2 * t4;
                        float v0 = d[mt][nt][h2 * 2]     + sbias[cl];
                        float v1 = d[mt][nt][h2 * 2 + 1] + sbias[cl + 1];
                        int gc = nb + cl;
                        int hh = gc >> 6, e = gc & 63;
                        size_t base = ((size_t)((m >> 9) * Hn + hh) * 64 + e) * 512
                                      + (size_t)(m & 511);
                        Cv[base]       = __float2half_rn(v0);
                        Cv[base + 512] = __float2half_rn(v1);
                    }
                }
            } else if (TOUT) {
                __half* crow = (__half*)Cp + (size_t)m * ldc + n0;
                #pragma unroll
                for (int nt = 0; nt < NT; nt++) {
                    int cl = colw + nt * 8 + 2 * t4;
                    float v0 = d[mt][nt][h2 * 2]     + sbias[cl];
                    float v1 = d[mt][nt][h2 * 2 + 1] + sbias[cl + 1];
                    if (RELU) { v0 = fmaxf(v0, 0.f); v1 = fmaxf(v1, 0.f); }
                    *(__half2*)(crow + cl) = __floats2half2_rn(v0, v1);
                }
            } else {
                float* crow = (float*)Cp + (size_t)m * ldc + n0;
                __half* trow = (Ct != nullptr) ? (Ct + (size_t)m * ldc + n0) : nullptr;
                const float* rrow = RES ? (Res + (size_t)m * ldc + n0) : nullptr;
                #pragma unroll
                for (int nt = 0; nt < NT; nt++) {
                    int cl = colw + nt * 8 + 2 * t4;
                    float v0 = d[mt][nt][h2 * 2]     * scale;
                    float v1 = d[mt][nt][h2 * 2 + 1] * scale;
                    if (bias != nullptr) { v0 += sbias[cl]; v1 += sbias[cl + 1]; }
                    if (RELU) { v0 = fmaxf(v0, 0.f); v1 = fmaxf(v1, 0.f); }
                    if (RES) {
                        float2 r = *(const float2*)(rrow + cl);
                        v0 += r.x; v1 += r.y;
                    }
                    *(float2*)(crow + cl) = make_float2(v0, v1);
                    if (Ct != nullptr)
                        *(__half2*)(trow + cl) = __floats2half2_rn(v0, v1);
                }
            }
        }
    }
}

// ============================================================
// flash attention (fp16 operands, fp32 accum/softmax), ldmatrix frag loads
// per (b,h,qtile 128); 256 threads; smem 96KB.
// ============================================================
#define FLASH_SMEM 98304
#define NEG_INF (-1e30f)

__global__ __launch_bounds__(256) void flash_kernel()
{
    extern __shared__ __half smh[];
    __half* Ps = smh;                          // 16384 halves

    const int t = threadIdx.x;
    const int lane = t & 31, w = t >> 5;
    const int g = lane >> 2, t4 = lane & 3;
    const int jj  = lane >> 3;
    const int rA  = ((jj & 1) << 3) + (lane & 7);
    const int kA  = (jj >> 1) << 3;
    const int rB  = lane & 7;
    const int ntO = jj >> 1;
    const int kB_ = (jj & 1) << 3;
    const int q0 = blockIdx.x * 128;
    const int b = blockIdx.y >> 3, h = blockIdx.y & 7;
    const int r0 = w * 16;

    const __half* qg = g_q  + (size_t)(b * Sn + q0) * Dn + h * HDn;
    const __half* kg = g_k  + (size_t)(b * Sn) * Dn + h * HDn;
    const __half* vg = g_vT + (size_t)(b * Hn + h) * HDn * Sn;

    // ---- stage Q into Ps chunk0: [128 q][64 e] ----
    #pragma unroll
    for (int i = 0; i < 4; i++) {
        int j = t + 256 * i;
        int r = j >> 3, f = j & 7;
        uint32_t dst = su32(&Ps[(r << 6) + (((f ^ r) & 7) << 3)]);
        cp_async16(dst, qg + (size_t)r * Dn + (f << 3));
    }
    CP_COMMIT();

    auto load_kv = [&](int tile, int st) {
        __half* kb = smh + 16384 + st * 16384;
        __half* vb = kb + 8192;
        #pragma unroll
        for (int i = 0; i < 4; i++) {          // K tile [128 s][64 e]
            int j = t + 256 * i;
            int r = j >> 3, f = j & 7;
            uint32_t dst = su32(&kb[(r << 6) + (((f ^ r) & 7) << 3)]);
            cp_async16(dst, kg + (size_t)(tile * 128 + r) * Dn + (f << 3));
        }
        #pragma unroll
        for (int i = 0; i < 4; i++) {          // V^T tile [64 e][128 s] -> 2 chunks
            int j = t + 256 * i;
            int e = j >> 4, f = j & 15;
            int ss = f >> 3, fc = f & 7;
            uint32_t dst = su32(&vb[ss * 4096 + (e << 6) + (((fc ^ e) & 7) << 3)]);
            cp_async16(dst, vg + (size_t)e * Sn + tile * 128 + (f << 3));
        }
        CP_COMMIT();
    };
    load_kv(0, 0);
    load_kv(1, 1);

    // ---- Q fragments (held in regs) ----
    CP_WAIT(2);
    __syncthreads();
    uint32_t qf[4][4];
    {
        uint32_t ps_u = su32(Ps);
        #pragma unroll
        for (int k16 = 0; k16 < 4; k16++) {
            const int kb = k16 << 4;
            LDSM4(qf[k16][0], qf[k16][1], qf[k16][2], qf[k16][3],
                  ps_u + (swzh(r0 + rA, kb + kA) << 1));
        }
    }
    __syncthreads();

    float m0 = NEG_INF, m1 = NEG_INF, l0 = 0.f, l1 = 0.f;
    float o[8][4] = {};
    const uint32_t ps_u = su32(Ps);

    for (int tile = 0; tile < 4; tile++) {
        if (tile < 3) { CP_WAIT(1); } else { CP_WAIT(0); }
        __syncthreads();
        const __half* kbp = smh + 16384 + (tile & 1) * 16384;
        const uint32_t kb_u = su32(kbp);
        const uint32_t vb_u = kb_u + 8192 * 2;

        // ---- S = Q K^T ----
        float s[16][4];
        #pragma unroll
        for (int nt = 0; nt < 16; nt++)
            #pragma unroll
            for (int j = 0; j < 4; j++) s[nt][j] = 0.f;
        #pragma unroll
        for (int k16 = 0; k16 < 4; k16++) {
            const int kk = k16 << 4;
            #pragma unroll
            for (int np = 0; np < 8; np++) {
                uint32_t b00, b01, b10, b11;
                int n = ((np * 2 + ntO) << 3) + rB;
                LDSM4(b00, b01, b10, b11, kb_u + (swzh(n, kk + kB_) << 1));
                MMA16(s[np * 2],     qf[k16], b00, b01);
                MMA16(s[np * 2 + 1], qf[k16], b10, b11);
            }
        }

        // ---- online softmax update ----
        float rm0 = NEG_INF, rm1 = NEG_INF;
        #pragma unroll
        for (int nt = 0; nt < 16; nt++) {
            s[nt][0] *= 0.125f; s[nt][1] *= 0.125f;
            s[nt][2] *= 0.125f; s[nt][3] *= 0.125f;
            rm0 = fmaxf(rm0, fmaxf(s[nt][0], s[nt][1]));
            rm1 = fmaxf(rm1, fmaxf(s[nt][2], s[nt][3]));
        }
        rm0 = fmaxf(rm0, __shfl_xor_sync(0xFFFFFFFF, rm0, 1));
        rm0 = fmaxf(rm0, __shfl_xor_sync(0xFFFFFFFF, rm0, 2));
        rm1 = fmaxf(rm1, __shfl_xor_sync(0xFFFFFFFF, rm1, 1));
        rm1 = fmaxf(rm1, __shfl_xor_sync(0xFFFFFFFF, rm1, 2));
        float mn0 = fmaxf(m0, rm0), mn1 = fmaxf(m1, rm1);
        float a0 = __expf(m0 - mn0), a1 = __expf(m1 - mn1);
        m0 = mn0; m1 = mn1;

        float rs0 = 0.f, rs1 = 0.f;
        #pragma unroll
        for (int nt = 0; nt < 16; nt++) {
            float p0 = __expf(s[nt][0] - m0);
            float p1 = __expf(s[nt][1] - m0);
            float p2 = __expf(s[nt][2] - m1);
            float p3 = __expf(s[nt][3] - m1);
            rs0 += p0 + p1; rs1 += p2 + p3;
            int col = nt * 8 + 2 * t4;
            int ch = col >> 6, kc = col & 63;
            *(__half2*)&Ps[ch * 8192 + swzh(r0 + g, kc)]     = __floats2half2_rn(p0, p1);
            *(__half2*)&Ps[ch * 8192 + swzh(r0 + g + 8, kc)] = __floats2half2_rn(p2, p3);
        }
        rs0 += __shfl_xor_sync(0xFFFFFFFF, rs0, 1);
        rs0 += __shfl_xor_sync(0xFFFFFFFF, rs0, 2);
        rs1 += __shfl_xor_sync(0xFFFFFFFF, rs1, 1);
        rs1 += __shfl_xor_sync(0xFFFFFFFF, rs1, 2);
        l0 = l0 * a0 + rs0;
        l1 = l1 * a1 + rs1;
        #pragma unroll
        for (int nt = 0; nt < 8; nt++) {
            o[nt][0] *= a0; o[nt][1] *= a0;
            o[nt][2] *= a1; o[nt][3] *= a1;
        }
        __syncwarp();

        // ---- O += P @ V^T ----
        #pragma unroll
        for (int ks = 0; ks < 8; ks++) {
            const int ch = ks >> 2, kk = (ks << 4) & 63;
            uint32_t af[4];
            LDSM4(af[0], af[1], af[2], af[3],
                  ps_u + ch * 16384 + (swzh(r0 + rA, kk + kA) << 1));
            #pragma unroll
            for (int np = 0; np < 4; np++) {
                uint32_t b00, b01, b10, b11;
                int n = ((np * 2 + ntO) << 3) + rB;
                LDSM4(b00, b01, b10, b11, vb_u + ch * 8192 + (swzh(n, kk + kB_) << 1));
                MMA16(o[np * 2],     af, b00, b01);
                MMA16(o[np * 2 + 1], af, b10, b11);
            }
        }
        __syncthreads();
        if (tile + 2 < 4) load_kv(tile + 2, tile & 1);
    }

    // ---- epilogue: O / l -> g_att (fp16) ----
    float inv0 = 1.0f / l0, inv1 = 1.0f / l1;
    __half* orow0 = g_att + (size_t)(b * Sn + q0 + r0 + g) * Dn + h * HDn;
    __half* orow1 = orow0 + 8 * Dn;
    #pragma unroll
    for (int nt = 0; nt < 8; nt++) {
        int col = nt * 8 + 2 * t4;
        *(__half2*)(orow0 + col) = __floats2half2_rn(o[nt][0] * inv0, o[nt][1] * inv0);
        *(__half2*)(orow1 + col) = __floats2half2_rn(o[nt][2] * inv1, o[nt][3] * inv1);
    }
}

// ============================================================
// weight transpose -> fp16: dst[zdst + c*R + r] = h(src[z][r][c])
// ============================================================
__global__ void transpose_kernel(const float* __restrict__ src, __half* __restrict__ dst,
                                 int R, int C, size_t zstride, size_t doff)
{
    __shared__ float tile[32][33];
    size_t zsrc = (size_t)blockIdx.z * R * C;
    size_t zdst = (size_t)blockIdx.z * zstride + doff;
    int c0 = blockIdx.x * 32, r0 = blockIdx.y * 32;
    int tx = threadIdx.x, ty = threadIdx.y;       // 32 x 8
    #pragma unroll
    for (int j = 0; j < 32; j += 8)
        tile[ty + j][tx] = src[zsrc + (size_t)(r0 + ty + j) * C + c0 + tx];
    __syncthreads();
    #pragma unroll
    for (int j = 0; j < 32; j += 8)
        dst[zdst + (size_t)(c0 + ty + j) * R + r0 + tx] = __float2half_rn(tile[tx][ty + j]);
}

__global__ void packbias_kernel(const float* __restrict__ bq, const float* __restrict__ bk,
                                const float* __restrict__ bv, float* __restrict__ dst)
{
    int i = blockIdx.x, t = threadIdx.x;   // Ln x 512
    dst[i * 1536 + t]        = bq[i * 512 + t];
    dst[i * 1536 + 512 + t]  = bk[i * 512 + t];
    dst[i * 1536 + 1024 + t] = bv[i * 512 + t];
}

// ============================================================
// build x = class_proj(concat(embed[idx], nd)); writes fp32 + fp16 shadow
// ============================================================
__global__ void build_x_kernel(const float* __restrict__ sol,
                               const float* __restrict__ cap,
                               const float* __restrict__ emb,
                               const float* __restrict__ srcW, const float* __restrict__ srcB,
                               const float* __restrict__ candW, const float* __restrict__ candB,
                               const float* __restrict__ depW, const float* __restrict__ depB)
{
    int row = blockIdx.x;
    int b = row / Sn, s = row % Sn;
    __shared__ float xin[INDIM];
    int t = threadIdx.x;

    int idx = (int)sol[(size_t)row * 4 + 0];
    xin[t] = emb[(size_t)idx * Cn + t];
    if (t == 0) {
        float rem = sol[(size_t)(b * Sn) * 4 + 3];
        float nd = (s == 0) ? 0.0f : 2.0f * (sol[(size_t)row * 4 + 2] - rem) / cap[b];
        xin[Cn] = nd;
    }
    __syncthreads();

    const float* W; const float* bb;
    if (s == 0)           { W = srcW;  bb = srcB;  }
    else if (s == Sn - 1) { W = depW;  bb = depB;  }
    else                  { W = candW; bb = candB; }

    int c = t;
    float acc0 = bb[c], acc1 = bb[c + 256];
    #pragma unroll 4
    for (int k = 0; k < INDIM; k++) {
        float xv = xin[k];
        acc0 += xv * W[k * Dn + c];
        acc1 += xv * W[k * Dn + c + 256];
    }
    g_x [(size_t)row * Dn + c]       = acc0;
    g_x [(size_t)row * Dn + c + 256] = acc1;
    g_xt[(size_t)row * Dn + c]       = __float2half_rn(acc0);
    g_xt[(size_t)row * Dn + c + 256] = __float2half_rn(acc1);
}

// ============================================================
// feasibility head
// ============================================================
__global__ void feas_kernel(const float* __restrict__ fW,
                            const float* __restrict__ fB,
                            float* __restrict__ out)
{
    int s = blockIdx.x + 1;
    int b = blockIdx.y;
    const float* xr = g_x + (size_t)(b * Sn + s) * Dn;
    int t = threadIdx.x;
    float acc = 0.f;
    #pragma unroll 4
    for (int k = t; k < Dn; k += 128) acc += xr[k] * fW[k];
    __shared__ float red[128];
    red[t] = acc; __syncthreads();
    for (int o = 64; o > 0; o >>= 1) {
        if (t < o) red[t] += red[t + o];
        __syncthreads();
    }
    if (t == 0) out[OUT_FEAS_OFF + b * 510 + (s - 1)] = red[0] + fB[0];
}

// ============================================================
// pointer logits
// ============================================================
__global__ void logits_kernel(const float* __restrict__ pW,
                              const float* __restrict__ pB,
                              float* __restrict__ out)
{
    int s = blockIdx.x + 1;
    int b = blockIdx.y;
    const float* xr = g_x + (size_t)(b * Sn + s) * Dn;
    int t = threadIdx.x;
    float a0 = 0.f, a1 = 0.f;
    #pragma unroll 4
    for (int k = t; k < Dn; k += 128) {
        float xv = xr[k];
        a0 += xv * pW[k * 2 + 0];
        a1 += xv * pW[k * 2 + 1];
    }
    __shared__ float r0[128], r1[128];
    r0[t] = a0; r1[t] = a1; __syncthreads();
    for (int o = 64; o > 0; o >>= 1) {
        if (t < o) { r0[t] += r0[t + o]; r1[t] += r1[t + o]; }
        __syncthreads();
    }
    if (t == 0) {
        out[b * OUT_LOGITS_PER_B + (s - 1)]       = r0[0] + pB[0];
        out[b * OUT_LOGITS_PER_B + 510 + (s - 1)] = r1[0] + pB[1];
    }
}

// ============================================================
// host orchestration
// ============================================================
extern "C" void kernel_launch(void* const* d_in, const int* in_sizes, int n_in,
                              void* d_out, int out_size)
{
    const float* sol   = (const float*)d_in[0];
    const float* cap   = (const float*)d_in[1];
    const float* emb   = (const float*)d_in[2];
    const float* srcW  = (const float*)d_in[3];
    const float* srcB  = (const float*)d_in[4];
    const float* candW = (const float*)d_in[5];
    const float* candB = (const float*)d_in[6];
    const float* depW  = (const float*)d_in[7];
    const float* depB  = (const float*)d_in[8];
    const float* feasW = (const float*)d_in[9];
    const float* feasB = (const float*)d_in[10];
    const float* Wq    = (const float*)d_in[11];
    const float* bq    = (const float*)d_in[12];
    const float* Wk    = (const float*)d_in[13];
    const float* bk    = (const float*)d_in[14];
    const float* Wv    = (const float*)d_in[15];
    const float* bv    = (const float*)d_in[16];
    const float* Wo    = (const float*)d_in[17];
    const float* bo    = (const float*)d_in[18];
    // d_in[19] = s_scale : softmax-shift-invariant, unused
    const float* W1    = (const float*)d_in[20];
    const float* b1    = (const float*)d_in[21];
    const float* W2    = (const float*)d_in[22];
    const float* b2    = (const float*)d_in[23];
    const float* ptrW  = (const float*)d_in[24];
    const float* ptrB  = (const float*)d_in[25];
    float* out = (float*)d_out;
    (void)in_sizes; (void)n_in; (void)out_size;

    float  *px;
    __half *pxt, *pq, *pk, *patt, *pvT, *ph;
    __half *pwqkvT, *pwoT, *pw1T, *pw2T;
    float  *pbqkv;
    cudaGetSymbolAddress((void**)&px,     g_x);
    cudaGetSymbolAddress((void**)&pxt,    g_xt);
    cudaGetSymbolAddress((void**)&pq,     g_q);
    cudaGetSymbolAddress((void**)&pk,     g_k);
    cudaGetSymbolAddress((void**)&patt,   g_att);
    cudaGetSymbolAddress((void**)&pvT,    g_vT);
    cudaGetSymbolAddress((void**)&ph,     g_h);
    cudaGetSymbolAddress((void**)&pwqkvT, g_wqkvT);
    cudaGetSymbolAddress((void**)&pbqkv,  g_bqkv);
    cudaGetSymbolAddress((void**)&pwoT,   g_woT);
    cudaGetSymbolAddress((void**)&pw1T,   g_w1T);
    cudaGetSymbolAddress((void**)&pw2T,   g_w2T);

    const int SM8 = 128 * 4 + 3 * (128 + 128) * 64 * 2;   // 98816
    const int SM4 = 64 * 4 + 3 * (128 + 64) * 64 * 2;     // 73984
    cudaFuncSetAttribute(mma_gemm<8, false, false, true,  false>, cudaFuncAttributeMaxDynamicSharedMemorySize, SM8);
    cudaFuncSetAttribute(mma_gemm<8, true,  false, false, true >, cudaFuncAttributeMaxDynamicSharedMemorySize, SM8);
    cudaFuncSetAttribute(mma_gemm<4, false, true,  false, false>, cudaFuncAttributeMaxDynamicSharedMemorySize, SM4);
    cudaFuncSetAttribute(flash_kernel, cudaFuncAttributeMaxDynamicSharedMemorySize, FLASH_SMEM);

    const size_t DD = (size_t)Dn * Dn;           // 262144
    const size_t DH = (size_t)Dn * HIDn;         // 1048576
    const size_t QKVS = (size_t)1536 * Dn;       // 786432

    // ---- pack weights (fp16): QKV concat [1536,512], others [N,K] ----
    dim3 tb(32, 8);
    transpose_kernel<<<dim3(16, 16, Ln), tb>>>(Wq, pwqkvT, Dn, Dn, QKVS, 0);
    transpose_kernel<<<dim3(16, 16, Ln), tb>>>(Wk, pwqkvT, Dn, Dn, QKVS, DD);
    transpose_kernel<<<dim3(16, 16, Ln), tb>>>(Wv, pwqkvT, Dn, Dn, QKVS, 2 * DD);
    transpose_kernel<<<dim3(16, 16, Ln), tb>>>(Wo, pwoT, Dn, Dn, DD, 0);
    transpose_kernel<<<dim3(64, 16, Ln), tb>>>(W1, pw1T, Dn, HIDn, DH, 0);
    transpose_kernel<<<dim3(16, 64, Ln), tb>>>(W2, pw2T, HIDn, Dn, DH, 0);
    packbias_kernel<<<Ln, 512>>>(bq, bk, bv, pbqkv);

    build_x_kernel<<<Mn, 256>>>(sol, cap, emb, srcW, srcB, candW, candB, depW, depB);

    const dim3 gQKV(12, 32, 1);     // 384 CTAs (BN=128)
    const dim3 gP4 (8, 32, 1);      // 256 CTAs (BN=64)
    const dim3 gFF1(16, 32, 1);     // 512 CTAs
    const dim3 gFl (4, 64, 1);      // 256 CTAs

    for (int i = 0; i < Ln; i++) {
        // ---- fused QKV projection (fp16 outputs; V per-head-transposed) ----
        mma_gemm<8, false, false, true, false><<<gQKV, 128, SM8>>>(
            pxt, Dn,  pwqkvT + i * QKVS, Dn,  pq, Dn,
            pbqkv + i * 1536, nullptr, 1.0f, Dn, pk, pvT, nullptr);

        // ---- flash attention ----
        flash_kernel<<<gFl, 256, FLASH_SMEM>>>();

        // ---- O projection + residual (writes x fp32 + xt fp16) ----
        mma_gemm<4, false, true, false, false><<<gP4, 128, SM4>>>(
            patt, Dn,  pwoT + i * DD, Dn,  px, Dn,
            bo + i * Dn, px, 1.0f, Dn, nullptr, nullptr, pxt);

        if (i == 0)
            feas_kernel<<<dim3(510, Bn), 128>>>(feasW, feasB, out);

        // ---- FFN (h stored fp16) ----
        mma_gemm<8, true, false, false, true><<<gFF1, 128, SM8>>>(
            pxt, Dn,  pw1T + i * DH, Dn,  ph, HIDn,
            b1 + i * HIDn, nullptr, 1.0f, Dn, nullptr, nullptr, nullptr);
        mma_gemm<4, false, true, false, false><<<gP4, 128, SM4>>>(
            ph, HIDn,  pw2T + i * DH, HIDn,  px, Dn,
            b2 + i * Dn, px, 1.0f, HIDn, nullptr, nullptr, pxt);
    }

    logits_kernel<<<dim3(510, Bn), 128>>>(ptrW, ptrB, out);
}

// round 12
// speedup vs baseline: 1.0079x; 1.0003x over previous
#include <cuda_runtime.h>
#include <cuda_fp16.h>
#include <cstdint>

// ---------------- problem constants ----------------
#define Bn   8
#define Sn   512
#define Ln   6
#define Dn   512
#define Hn   8
#define HDn  64
#define HIDn 2048
#define Cn   256
#define INDIM 257
#define Mn   (Bn * Sn)          // 4096 rows

#define OUT_LOGITS_PER_B 1020   // 2 * 510
#define OUT_FEAS_OFF     (Bn * OUT_LOGITS_PER_B)   // 8160

// ---------------- scratch (device globals; no allocation) ----------------
__device__ float  g_x  [Mn * Dn];            // residual stream (fp32)
__device__ __half g_xt [Mn * Dn];            // residual stream (fp16)
__device__ __half g_q  [Mn * Dn];            // Q (fp16)
__device__ __half g_k  [Mn * Dn];            // K (fp16)
__device__ __half g_att[Mn * Dn];            // attention out (fp16)
__device__ __half g_vT [Mn * Dn];            // V^T per head [b,h,e,s] (fp16)
__device__ __half g_h  [Mn * HIDn];          // FFN hidden (fp16)
// transposed weights ([N,K] K-major, fp16)
__device__ __half g_wqkvT[Ln * 1536 * Dn];   // concat QKV [1536,512] per layer
__device__ float  g_bqkv [Ln * 1536];
__device__ __half g_woT[Ln * Dn * Dn];
__device__ __half g_w1T[Ln * Dn * HIDn];
__device__ __half g_w2T[Ln * HIDn * Dn];

// ============================================================
// portable PTX helpers
// ============================================================
__device__ __forceinline__ uint32_t su32(const void* p) {
    uint32_t a;
    asm("{ .reg .u64 t; cvta.to.shared.u64 t, %1; cvt.u32.u64 %0, t; }" : "=r"(a) : "l"(p));
    return a;
}
__device__ __forceinline__ void cp_async16(uint32_t s, const void* g) {
    asm volatile("cp.async.cg.shared.global [%0], [%1], 16;" :: "r"(s), "l"(g));
}
#define CP_COMMIT() asm volatile("cp.async.commit_group;" ::: "memory")
#define CP_WAIT(n)  asm volatile("cp.async.wait_group %0;" :: "n"(n) : "memory")

// fp16 mma: D(f32) += A(f16) B(f16)^T ; A=4 regs (8 halves), B=2 regs (4 halves)
#define MMA16(dd, af, b0, b1) \
    asm volatile("mma.sync.aligned.m16n8k16.row.col.f32.f16.f16.f32 " \
        "{%0,%1,%2,%3}, {%4,%5,%6,%7}, {%8,%9}, {%0,%1,%2,%3};" \
        : "+f"((dd)[0]), "+f"((dd)[1]), "+f"((dd)[2]), "+f"((dd)[3]) \
        : "r"((af)[0]), "r"((af)[1]), "r"((af)[2]), "r"((af)[3]), "r"(b0), "r"(b1))

// ldmatrix x4: each lane supplies the address of one 16B row of an 8x8 b16 tile
#define LDSM4(r0, r1, r2, r3, addr) \
    asm volatile("ldmatrix.sync.aligned.m8n8.x4.shared.b16 {%0,%1,%2,%3}, [%4];" \
        : "=r"(r0), "=r"(r1), "=r"(r2), "=r"(r3) : "r"(addr))

// half-element index in a [row][64-half] tile (128B rows, 16B-chunk XOR swizzle)
__device__ __forceinline__ int swzh(int row, int k) {
    return (row << 6) + ((((k >> 3) ^ row) & 7) << 3) + (k & 7);
}
__device__ __forceinline__ uint32_t ldsu(const __half* p) {
    return *(const uint32_t*)p;
}

// ============================================================
// fp16 mma.sync GEMM: C = scale*(A B^T) (+bias, +Res, ReLU)
// CTA 128 x (NT*16); BK=64 halves; 3-stage cp.async; 128 threads; 2 CTAs/SM.
// ldmatrix.x4 fragment loads. QKV: epilogue routes q/k/vT (fp16).
// TOUT: C is fp16. Ct: fp16 shadow of C.
// ============================================================
template<int NT, bool RELU, bool RES, bool QKV, bool TOUT>
__global__ __launch_bounds__(128, 2) void mma_gemm(
    const __half* __restrict__ A, int lda,
    const __half* __restrict__ B, int ldb,
    void* __restrict__ Cp, int ldc,
    const float* __restrict__ bias, const float* __restrict__ Res,
    float scale, int K,
    __half* __restrict__ Ck, __half* __restrict__ Cv, __half* __restrict__ Ct)
{
    constexpr int BM = 128, BK = 64;
    constexpr int BN = NT * 16;
    constexpr int NSTAGE = 3;
    constexpr int STAGE_H = (BM + BN) * BK;      // halves per stage

    extern __shared__ float smem[];
    float* sbias = smem;
    __half* sdata = (__half*)(smem + BN);

    const int t = threadIdx.x;
    const int m0 = blockIdx.y * BM;
    const int n0 = blockIdx.x * BN;

    if (bias != nullptr && t < BN) sbias[t] = bias[n0 + t];

    auto load_stage = [&](int st, int k0) {
        __half* sa = sdata + (st % NSTAGE) * STAGE_H;
        __half* sb = sa + BM * BK;
        #pragma unroll
        for (int i = 0; i < 8; i++) {             // A: 128 rows x 8 chunks
            int j = t + 128 * i;
            int m = j >> 3, f = j & 7;
            uint32_t dst = su32(&sa[(m << 6) + (((f ^ m) & 7) << 3)]);
            cp_async16(dst, A + (size_t)(m0 + m) * lda + k0 + (f << 3));
        }
        #pragma unroll
        for (int i = 0; i < NT; i++) {            // B: BN rows x 8 chunks
            int j = t + 128 * i;
            int n = j >> 3, f = j & 7;
            uint32_t dst = su32(&sb[(n << 6) + (((f ^ n) & 7) << 3)]);
            cp_async16(dst, B + (size_t)(n0 + n) * ldb + k0 + (f << 3));
        }
        CP_COMMIT();
    };

    const int nst = K / BK;
    load_stage(0, 0);
    load_stage(1, BK);

    const int lane = t & 31, w = t >> 5;
    const int wm = w >> 1, wn = w & 1;
    const int g = lane >> 2, t4 = lane & 3;
    // ldmatrix lane->address constants
    const int jj  = lane >> 3;                   // 0..3 (matrix id)
    const int rA  = ((jj & 1) << 3) + (lane & 7);
    const int kA  = (jj >> 1) << 3;
    const int rB  = lane & 7;
    const int ntO = jj >> 1;                     // which nt of the pair
    const int kB_ = (jj & 1) << 3;

    float d[4][NT][4] = {};

    for (int s = 0; s < nst; s++) {
        if (s < nst - 1) { CP_WAIT(1); } else { CP_WAIT(0); }
        __syncthreads();
        if (s + 2 < nst) load_stage(s + 2, (s + 2) * BK);

        uint32_t sa_u = su32(sdata + (s % NSTAGE) * STAGE_H);
        uint32_t sb_u = sa_u + BM * BK * 2;
        #pragma unroll
        for (int k16 = 0; k16 < 4; k16++) {
            const int kb = k16 << 4;
            uint32_t af[4][4];
            #pragma unroll
            for (int mt = 0; mt < 4; mt++) {
                int r = wm * 64 + mt * 16 + rA;
                LDSM4(af[mt][0], af[mt][1], af[mt][2], af[mt][3],
                      sa_u + (swzh(r, kb + kA) << 1));
            }
            uint32_t bf[NT][2];
            #pragma unroll
            for (int np = 0; np < NT / 2; np++) {
                int n = wn * NT * 8 + ((np * 2 + ntO) << 3) + rB;
                LDSM4(bf[np * 2][0], bf[np * 2][1], bf[np * 2 + 1][0], bf[np * 2 + 1][1],
                      sb_u + (swzh(n, kb + kB_) << 1));
            }
            #pragma unroll
            for (int nt = 0; nt < NT; nt++)
                #pragma unroll
                for (int mt = 0; mt < 4; mt++) MMA16(d[mt][nt], af[mt], bf[nt][0], bf[nt][1]);
        }
    }

    // ---------------- epilogue ----------------
    const int colw = wn * NT * 8;
    #pragma unroll
    for (int mt = 0; mt < 4; mt++) {
        #pragma unroll
        for (int h2 = 0; h2 < 2; h2++) {
            const int m = m0 + wm * 64 + mt * 16 + g + h2 * 8;
            if (QKV) {
                const int region = n0 >> 9;       // 0=Q, 1=K, 2=V
                const int nb = n0 & 511;
                if (region < 2) {
                    __half* crow = (region == 0 ? (__half*)Cp : Ck) + (size_t)m * 512 + nb;
                    #pragma unroll
                    for (int nt = 0; nt < NT; nt++) {
                        int cl = colw + nt * 8 + 2 * t4;
                        float v0 = d[mt][nt][h2 * 2]     + sbias[cl];
                        float v1 = d[mt][nt][h2 * 2 + 1] + sbias[cl + 1];
                        *(__half2*)(crow + cl) = __floats2half2_rn(v0, v1);
                    }
                } else {
                    #pragma unroll
                    for (int nt = 0; nt < NT; nt++) {
                        int cl = colw + nt * 8 + 2 * t4;
                        float v0 = d[mt][nt][h2 * 2]     + sbias[cl];
                        float v1 = d[mt][nt][h2 * 2 + 1] + sbias[cl + 1];
                        int gc = nb + cl;
                        int hh = gc >> 6, e = gc & 63;
                        size_t base = ((size_t)((m >> 9) * Hn + hh) * 64 + e) * 512
                                      + (size_t)(m & 511);
                        Cv[base]       = __float2half_rn(v0);
                        Cv[base + 512] = __float2half_rn(v1);
                    }
                }
            } else if (TOUT) {
                __half* crow = (__half*)Cp + (size_t)m * ldc + n0;
                #pragma unroll
                for (int nt = 0; nt < NT; nt++) {
                    int cl = colw + nt * 8 + 2 * t4;
                    float v0 = d[mt][nt][h2 * 2]     + sbias[cl];
                    float v1 = d[mt][nt][h2 * 2 + 1] + sbias[cl + 1];
                    if (RELU) { v0 = fmaxf(v0, 0.f); v1 = fmaxf(v1, 0.f); }
                    *(__half2*)(crow + cl) = __floats2half2_rn(v0, v1);
                }
            } else {
                float* crow = (float*)Cp + (size_t)m * ldc + n0;
                __half* trow = (Ct != nullptr) ? (Ct + (size_t)m * ldc + n0) : nullptr;
                const float* rrow = RES ? (Res + (size_t)m * ldc + n0) : nullptr;
                #pragma unroll
                for (int nt = 0; nt < NT; nt++) {
                    int cl = colw + nt * 8 + 2 * t4;
                    float v0 = d[mt][nt][h2 * 2]     * scale;
                    float v1 = d[mt][nt][h2 * 2 + 1] * scale;
                    if (bias != nullptr) { v0 += sbias[cl]; v1 += sbias[cl + 1]; }
                    if (RELU) { v0 = fmaxf(v0, 0.f); v1 = fmaxf(v1, 0.f); }
                    if (RES) {
                        float2 r = *(const float2*)(rrow + cl);
                        v0 += r.x; v1 += r.y;
                    }
                    *(float2*)(crow + cl) = make_float2(v0, v1);
                    if (Ct != nullptr)
                        *(__half2*)(trow + cl) = __floats2half2_rn(v0, v1);
                }
            }
        }
    }
}

// ============================================================
// flash attention (fp16 operands, fp32 accum/softmax), ldmatrix frag loads
// per (b,h,qtile 128); 256 threads; smem 96KB.
// ============================================================
#define FLASH_SMEM 98304
#define NEG_INF (-1e30f)

__global__ __launch_bounds__(256) void flash_kernel()
{
    extern __shared__ __half smh[];
    __half* Ps = smh;                          // 16384 halves

    const int t = threadIdx.x;
    const int lane = t & 31, w = t >> 5;
    const int g = lane >> 2, t4 = lane & 3;
    const int jj  = lane >> 3;
    const int rA  = ((jj & 1) << 3) + (lane & 7);
    const int kA  = (jj >> 1) << 3;
    const int rB  = lane & 7;
    const int ntO = jj >> 1;
    const int kB_ = (jj & 1) << 3;
    const int q0 = blockIdx.x * 128;
    const int b = blockIdx.y >> 3, h = blockIdx.y & 7;
    const int r0 = w * 16;

    const __half* qg = g_q  + (size_t)(b * Sn + q0) * Dn + h * HDn;
    const __half* kg = g_k  + (size_t)(b * Sn) * Dn + h * HDn;
    const __half* vg = g_vT + (size_t)(b * Hn + h) * HDn * Sn;

    // ---- stage Q into Ps chunk0: [128 q][64 e] ----
    #pragma unroll
    for (int i = 0; i < 4; i++) {
        int j = t + 256 * i;
        int r = j >> 3, f = j & 7;
        uint32_t dst = su32(&Ps[(r << 6) + (((f ^ r) & 7) << 3)]);
        cp_async16(dst, qg + (size_t)r * Dn + (f << 3));
    }
    CP_COMMIT();

    auto load_kv = [&](int tile, int st) {
        __half* kb = smh + 16384 + st * 16384;
        __half* vb = kb + 8192;
        #pragma unroll
        for (int i = 0; i < 4; i++) {          // K tile [128 s][64 e]
            int j = t + 256 * i;
            int r = j >> 3, f = j & 7;
            uint32_t dst = su32(&kb[(r << 6) + (((f ^ r) & 7) << 3)]);
            cp_async16(dst, kg + (size_t)(tile * 128 + r) * Dn + (f << 3));
        }
        #pragma unroll
        for (int i = 0; i < 4; i++) {          // V^T tile [64 e][128 s] -> 2 chunks
            int j = t + 256 * i;
            int e = j >> 4, f = j & 15;
            int ss = f >> 3, fc = f & 7;
            uint32_t dst = su32(&vb[ss * 4096 + (e << 6) + (((fc ^ e) & 7) << 3)]);
            cp_async16(dst, vg + (size_t)e * Sn + tile * 128 + (f << 3));
        }
        CP_COMMIT();
    };
    load_kv(0, 0);
    load_kv(1, 1);

    // ---- Q fragments (held in regs) ----
    CP_WAIT(2);
    __syncthreads();
    uint32_t qf[4][4];
    {
        uint32_t ps_u = su32(Ps);
        #pragma unroll
        for (int k16 = 0; k16 < 4; k16++) {
            const int kb = k16 << 4;
            LDSM4(qf[k16][0], qf[k16][1], qf[k16][2], qf[k16][3],
                  ps_u + (swzh(r0 + rA, kb + kA) << 1));
        }
    }
    __syncthreads();

    float m0 = NEG_INF, m1 = NEG_INF, l0 = 0.f, l1 = 0.f;
    float o[8][4] = {};
    const uint32_t ps_u = su32(Ps);

    for (int tile = 0; tile < 4; tile++) {
        if (tile < 3) { CP_WAIT(1); } else { CP_WAIT(0); }
        __syncthreads();
        const __half* kbp = smh + 16384 + (tile & 1) * 16384;
        const uint32_t kb_u = su32(kbp);
        const uint32_t vb_u = kb_u + 8192 * 2;

        // ---- S = Q K^T ----
        float s[16][4];
        #pragma unroll
        for (int nt = 0; nt < 16; nt++)
            #pragma unroll
            for (int j = 0; j < 4; j++) s[nt][j] = 0.f;
        #pragma unroll
        for (int k16 = 0; k16 < 4; k16++) {
            const int kk = k16 << 4;
            #pragma unroll
            for (int np = 0; np < 8; np++) {
                uint32_t b00, b01, b10, b11;
                int n = ((np * 2 + ntO) << 3) + rB;
                LDSM4(b00, b01, b10, b11, kb_u + (swzh(n, kk + kB_) << 1));
                MMA16(s[np * 2],     qf[k16], b00, b01);
                MMA16(s[np * 2 + 1], qf[k16], b10, b11);
            }
        }

        // ---- online softmax update ----
        float rm0 = NEG_INF, rm1 = NEG_INF;
        #pragma unroll
        for (int nt = 0; nt < 16; nt++) {
            s[nt][0] *= 0.125f; s[nt][1] *= 0.125f;
            s[nt][2] *= 0.125f; s[nt][3] *= 0.125f;
            rm0 = fmaxf(rm0, fmaxf(s[nt][0], s[nt][1]));
            rm1 = fmaxf(rm1, fmaxf(s[nt][2], s[nt][3]));
        }
        rm0 = fmaxf(rm0, __shfl_xor_sync(0xFFFFFFFF, rm0, 1));
        rm0 = fmaxf(rm0, __shfl_xor_sync(0xFFFFFFFF, rm0, 2));
        rm1 = fmaxf(rm1, __shfl_xor_sync(0xFFFFFFFF, rm1, 1));
        rm1 = fmaxf(rm1, __shfl_xor_sync(0xFFFFFFFF, rm1, 2));
        float mn0 = fmaxf(m0, rm0), mn1 = fmaxf(m1, rm1);
        float a0 = __expf(m0 - mn0), a1 = __expf(m1 - mn1);
        m0 = mn0; m1 = mn1;

        float rs0 = 0.f, rs1 = 0.f;
        #pragma unroll
        for (int nt = 0; nt < 16; nt++) {
            float p0 = __expf(s[nt][0] - m0);
            float p1 = __expf(s[nt][1] - m0);
            float p2 = __expf(s[nt][2] - m1);
            float p3 = __expf(s[nt][3] - m1);
            rs0 += p0 + p1; rs1 += p2 + p3;
            int col = nt * 8 + 2 * t4;
            int ch = col >> 6, kc = col & 63;
            *(__half2*)&Ps[ch * 8192 + swzh(r0 + g, kc)]     = __floats2half2_rn(p0, p1);
            *(__half2*)&Ps[ch * 8192 + swzh(r0 + g + 8, kc)] = __floats2half2_rn(p2, p3);
        }
        rs0 += __shfl_xor_sync(0xFFFFFFFF, rs0, 1);
        rs0 += __shfl_xor_sync(0xFFFFFFFF, rs0, 2);
        rs1 += __shfl_xor_sync(0xFFFFFFFF, rs1, 1);
        rs1 += __shfl_xor_sync(0xFFFFFFFF, rs1, 2);
        l0 = l0 * a0 + rs0;
        l1 = l1 * a1 + rs1;
        #pragma unroll
        for (int nt = 0; nt < 8; nt++) {
            o[nt][0] *= a0; o[nt][1] *= a0;
            o[nt][2] *= a1; o[nt][3] *= a1;
        }
        __syncwarp();

        // ---- O += P @ V^T ----
        #pragma unroll
        for (int ks = 0; ks < 8; ks++) {
            const int ch = ks >> 2, kk = (ks << 4) & 63;
            uint32_t af[4];
            LDSM4(af[0], af[1], af[2], af[3],
                  ps_u + ch * 16384 + (swzh(r0 + rA, kk + kA) << 1));
            #pragma unroll
            for (int np = 0; np < 4; np++) {
                uint32_t b00, b01, b10, b11;
                int n = ((np * 2 + ntO) << 3) + rB;
                LDSM4(b00, b01, b10, b11, vb_u + ch * 8192 + (swzh(n, kk + kB_) << 1));
                MMA16(o[np * 2],     af, b00, b01);
                MMA16(o[np * 2 + 1], af, b10, b11);
            }
        }
        __syncthreads();
        if (tile + 2 < 4) load_kv(tile + 2, tile & 1);
    }

    // ---- epilogue: O / l -> g_att (fp16) ----
    float inv0 = 1.0f / l0, inv1 = 1.0f / l1;
    __half* orow0 = g_att + (size_t)(b * Sn + q0 + r0 + g) * Dn + h * HDn;
    __half* orow1 = orow0 + 8 * Dn;
    #pragma unroll
    for (int nt = 0; nt < 8; nt++) {
        int col = nt * 8 + 2 * t4;
        *(__half2*)(orow0 + col) = __floats2half2_rn(o[nt][0] * inv0, o[nt][1] * inv0);
        *(__half2*)(orow1 + col) = __floats2half2_rn(o[nt][2] * inv1, o[nt][3] * inv1);
    }
}

// ============================================================
// weight transpose -> fp16: dst[zdst + c*R + r] = h(src[z][r][c])
// ============================================================
__global__ void transpose_kernel(const float* __restrict__ src, __half* __restrict__ dst,
                                 int R, int C, size_t zstride, size_t doff)
{
    __shared__ float tile[32][33];
    size_t zsrc = (size_t)blockIdx.z * R * C;
    size_t zdst = (size_t)blockIdx.z * zstride + doff;
    int c0 = blockIdx.x * 32, r0 = blockIdx.y * 32;
    int tx = threadIdx.x, ty = threadIdx.y;       // 32 x 8
    #pragma unroll
    for (int j = 0; j < 32; j += 8)
        tile[ty + j][tx] = src[zsrc + (size_t)(r0 + ty + j) * C + c0 + tx];
    __syncthreads();
    #pragma unroll
    for (int j = 0; j < 32; j += 8)
        dst[zdst + (size_t)(c0 + ty + j) * R + r0 + tx] = __float2half_rn(tile[tx][ty + j]);
}

__global__ void packbias_kernel(const float* __restrict__ bq, const float* __restrict__ bk,
                                const float* __restrict__ bv, float* __restrict__ dst)
{
    int i = blockIdx.x, t = threadIdx.x;   // Ln x 512
    dst[i * 1536 + t]        = bq[i * 512 + t];
    dst[i * 1536 + 512 + t]  = bk[i * 512 + t];
    dst[i * 1536 + 1024 + t] = bv[i * 512 + t];
}

// ============================================================
// build x = class_proj(concat(embed[idx], nd)); writes fp32 + fp16 shadow
// ============================================================
__global__ void build_x_kernel(const float* __restrict__ sol,
                               const float* __restrict__ cap,
                               const float* __restrict__ emb,
                               const float* __restrict__ srcW, const float* __restrict__ srcB,
                               const float* __restrict__ candW, const float* __restrict__ candB,
                               const float* __restrict__ depW, const float* __restrict__ depB)
{
    int row = blockIdx.x;
    int b = row / Sn, s = row % Sn;
    __shared__ float xin[INDIM];
    int t = threadIdx.x;

    int idx = (int)sol[(size_t)row * 4 + 0];
    xin[t] = emb[(size_t)idx * Cn + t];
    if (t == 0) {
        float rem = sol[(size_t)(b * Sn) * 4 + 3];
        float nd = (s == 0) ? 0.0f : 2.0f * (sol[(size_t)row * 4 + 2] - rem) / cap[b];
        xin[Cn] = nd;
    }
    __syncthreads();

    const float* W; const float* bb;
    if (s == 0)           { W = srcW;  bb = srcB;  }
    else if (s == Sn - 1) { W = depW;  bb = depB;  }
    else                  { W = candW; bb = candB; }

    int c = t;
    float acc0 = bb[c], acc1 = bb[c + 256];
    #pragma unroll 4
    for (int k = 0; k < INDIM; k++) {
        float xv = xin[k];
        acc0 += xv * W[k * Dn + c];
        acc1 += xv * W[k * Dn + c + 256];
    }
    g_x [(size_t)row * Dn + c]       = acc0;
    g_x [(size_t)row * Dn + c + 256] = acc1;
    g_xt[(size_t)row * Dn + c]       = __float2half_rn(acc0);
    g_xt[(size_t)row * Dn + c + 256] = __float2half_rn(acc1);
}

// ============================================================
// feasibility head
// ============================================================
__global__ void feas_kernel(const float* __restrict__ fW,
                            const float* __restrict__ fB,
                            float* __restrict__ out)
{
    int s = blockIdx.x + 1;
    int b = blockIdx.y;
    const float* xr = g_x + (size_t)(b * Sn + s) * Dn;
    int t = threadIdx.x;
    float acc = 0.f;
    #pragma unroll 4
    for (int k = t; k < Dn; k += 128) acc += xr[k] * fW[k];
    __shared__ float red[128];
    red[t] = acc; __syncthreads();
    for (int o = 64; o > 0; o >>= 1) {
        if (t < o) red[t] += red[t + o];
        __syncthreads();
    }
    if (t == 0) out[OUT_FEAS_OFF + b * 510 + (s - 1)] = red[0] + fB[0];
}

// ============================================================
// pointer logits
// ============================================================
__global__ void logits_kernel(const float* __restrict__ pW,
                              const float* __restrict__ pB,
                              float* __restrict__ out)
{
    int s = blockIdx.x + 1;
    int b = blockIdx.y;
    const float* xr = g_x + (size_t)(b * Sn + s) * Dn;
    int t = threadIdx.x;
    float a0 = 0.f, a1 = 0.f;
    #pragma unroll 4
    for (int k = t; k < Dn; k += 128) {
        float xv = xr[k];
        a0 += xv * pW[k * 2 + 0];
        a1 += xv * pW[k * 2 + 1];
    }
    __shared__ float r0[128], r1[128];
    r0[t] = a0; r1[t] = a1; __syncthreads();
    for (int o = 64; o > 0; o >>= 1) {
        if (t < o) { r0[t] += r0[t + o]; r1[t] += r1[t + o]; }
        __syncthreads();
    }
    if (t == 0) {
        out[b * OUT_LOGITS_PER_B + (s - 1)]       = r0[0] + pB[0];
        out[b * OUT_LOGITS_PER_B + 510 + (s - 1)] = r1[0] + pB[1];
    }
}

// ============================================================
// host orchestration
// ============================================================
extern "C" void kernel_launch(void* const* d_in, const int* in_sizes, int n_in,
                              void* d_out, int out_size)
{
    const float* sol   = (const float*)d_in[0];
    const float* cap   = (const float*)d_in[1];
    const float* emb   = (const float*)d_in[2];
    const float* srcW  = (const float*)d_in[3];
    const float* srcB  = (const float*)d_in[4];
    const float* candW = (const float*)d_in[5];
    const float* candB = (const float*)d_in[6];
    const float* depW  = (const float*)d_in[7];
    const float* depB  = (const float*)d_in[8];
    const float* feasW = (const float*)d_in[9];
    const float* feasB = (const float*)d_in[10];
    const float* Wq    = (const float*)d_in[11];
    const float* bq    = (const float*)d_in[12];
    const float* Wk    = (const float*)d_in[13];
    const float* bk    = (const float*)d_in[14];
    const float* Wv    = (const float*)d_in[15];
    const float* bv    = (const float*)d_in[16];
    const float* Wo    = (const float*)d_in[17];
    const float* bo    = (const float*)d_in[18];
    // d_in[19] = s_scale : softmax-shift-invariant, unused
    const float* W1    = (const float*)d_in[20];
    const float* b1    = (const float*)d_in[21];
    const float* W2    = (const float*)d_in[22];
    const float* b2    = (const float*)d_in[23];
    const float* ptrW  = (const float*)d_in[24];
    const float* ptrB  = (const float*)d_in[25];
    float* out = (float*)d_out;
    (void)in_sizes; (void)n_in; (void)out_size;

    float  *px;
    __half *pxt, *pq, *pk, *patt, *pvT, *ph;
    __half *pwqkvT, *pwoT, *pw1T, *pw2T;
    float  *pbqkv;
    cudaGetSymbolAddress((void**)&px,     g_x);
    cudaGetSymbolAddress((void**)&pxt,    g_xt);
    cudaGetSymbolAddress((void**)&pq,     g_q);
    cudaGetSymbolAddress((void**)&pk,     g_k);
    cudaGetSymbolAddress((void**)&patt,   g_att);
    cudaGetSymbolAddress((void**)&pvT,    g_vT);
    cudaGetSymbolAddress((void**)&ph,     g_h);
    cudaGetSymbolAddress((void**)&pwqkvT, g_wqkvT);
    cudaGetSymbolAddress((void**)&pbqkv,  g_bqkv);
    cudaGetSymbolAddress((void**)&pwoT,   g_woT);
    cudaGetSymbolAddress((void**)&pw1T,   g_w1T);
    cudaGetSymbolAddress((void**)&pw2T,   g_w2T);

    const int SM8 = 128 * 4 + 3 * (128 + 128) * 64 * 2;   // 98816
    const int SM4 = 64 * 4 + 3 * (128 + 64) * 64 * 2;     // 73984
    cudaFuncSetAttribute(mma_gemm<8, false, false, true,  false>, cudaFuncAttributeMaxDynamicSharedMemorySize, SM8);
    cudaFuncSetAttribute(mma_gemm<8, true,  false, false, true >, cudaFuncAttributeMaxDynamicSharedMemorySize, SM8);
    cudaFuncSetAttribute(mma_gemm<4, false, true,  false, false>, cudaFuncAttributeMaxDynamicSharedMemorySize, SM4);
    cudaFuncSetAttribute(flash_kernel, cudaFuncAttributeMaxDynamicSharedMemorySize, FLASH_SMEM);

    const size_t DD = (size_t)Dn * Dn;           // 262144
    const size_t DH = (size_t)Dn * HIDn;         // 1048576
    const size_t QKVS = (size_t)1536 * Dn;       // 786432

    // ---- pack weights (fp16): QKV concat [1536,512], others [N,K] ----
    dim3 tb(32, 8);
    transpose_kernel<<<dim3(16, 16, Ln), tb>>>(Wq, pwqkvT, Dn, Dn, QKVS, 0);
    transpose_kernel<<<dim3(16, 16, Ln), tb>>>(Wk, pwqkvT, Dn, Dn, QKVS, DD);
    transpose_kernel<<<dim3(16, 16, Ln), tb>>>(Wv, pwqkvT, Dn, Dn, QKVS, 2 * DD);
    transpose_kernel<<<dim3(16, 16, Ln), tb>>>(Wo, pwoT, Dn, Dn, DD, 0);
    transpose_kernel<<<dim3(64, 16, Ln), tb>>>(W1, pw1T, Dn, HIDn, DH, 0);
    transpose_kernel<<<dim3(16, 64, Ln), tb>>>(W2, pw2T, HIDn, Dn, DH, 0);
    packbias_kernel<<<Ln, 512>>>(bq, bk, bv, pbqkv);

    build_x_kernel<<<Mn, 256>>>(sol, cap, emb, srcW, srcB, candW, candB, depW, depB);

    const dim3 gQKV(12, 32, 1);     // 384 CTAs (BN=128)
    const dim3 gP4 (8, 32, 1);      // 256 CTAs (BN=64)
    const dim3 gFF1(16, 32, 1);     // 512 CTAs
    const dim3 gFl (4, 64, 1);      // 256 CTAs

    for (int i = 0; i < Ln; i++) {
        // ---- fused QKV projection (fp16 outputs; V per-head-transposed) ----
        mma_gemm<8, false, false, true, false><<<gQKV, 128, SM8>>>(
            pxt, Dn,  pwqkvT + i * QKVS, Dn,  pq, Dn,
            pbqkv + i * 1536, nullptr, 1.0f, Dn, pk, pvT, nullptr);

        // ---- flash attention ----
        flash_kernel<<<gFl, 256, FLASH_SMEM>>>();

        // ---- O projection + residual (writes x fp32 + xt fp16) ----
        mma_gemm<4, false, true, false, false><<<gP4, 128, SM4>>>(
            patt, Dn,  pwoT + i * DD, Dn,  px, Dn,
            bo + i * Dn, px, 1.0f, Dn, nullptr, nullptr, pxt);

        if (i == 0)
            feas_kernel<<<dim3(510, Bn), 128>>>(feasW, feasB, out);

        // ---- FFN (h stored fp16) ----
        mma_gemm<8, true, false, false, true><<<gFF1, 128, SM8>>>(
            pxt, Dn,  pw1T + i * DH, Dn,  ph, HIDn,
            b1 + i * HIDn, nullptr, 1.0f, Dn, nullptr, nullptr, nullptr);
        mma_gemm<4, false, true, false, false><<<gP4, 128, SM4>>>(
            ph, HIDn,  pw2T + i * DH, HIDn,  px, Dn,
            b2 + i * Dn, px, 1.0f, HIDn, nullptr, nullptr, pxt);
    }

    logits_kernel<<<dim3(510, Bn), 128>>>(ptrW, ptrB, out);
}

// round 13
// speedup vs baseline: 1.0080x; 1.0001x over previous
#include <cuda_runtime.h>
#include <cuda_fp16.h>
#include <cstdint>

// ---------------- problem constants ----------------
#define Bn   8
#define Sn   512
#define Ln   6
#define Dn   512
#define Hn   8
#define HDn  64
#define HIDn 2048
#define Cn   256
#define INDIM 257
#define Mn   (Bn * Sn)          // 4096 rows

#define OUT_LOGITS_PER_B 1020   // 2 * 510
#define OUT_FEAS_OFF     (Bn * OUT_LOGITS_PER_B)   // 8160

// ---------------- scratch (device globals; no allocation) ----------------
__device__ float  g_x  [Mn * Dn];            // residual stream (fp32)
__device__ __half g_xt [Mn * Dn];            // residual stream (fp16)
__device__ __half g_q  [Mn * Dn];            // Q (fp16)
__device__ __half g_k  [Mn * Dn];            // K (fp16)
__device__ __half g_att[Mn * Dn];            // attention out (fp16)
__device__ __half g_vT [Mn * Dn];            // V^T per head [b,h,e,s] (fp16)
__device__ __half g_h  [Mn * HIDn];          // FFN hidden (fp16)
// transposed weights ([N,K] K-major, fp16)
__device__ __half g_wqkvT[Ln * 1536 * Dn];   // concat QKV [1536,512] per layer
__device__ float  g_bqkv [Ln * 1536];
__device__ __half g_woT[Ln * Dn * Dn];
__device__ __half g_w1T[Ln * Dn * HIDn];
__device__ __half g_w2T[Ln * HIDn * Dn];

// ============================================================
// portable PTX helpers
// ============================================================
__device__ __forceinline__ uint32_t su32(const void* p) {
    uint32_t a;
    asm("{ .reg .u64 t; cvta.to.shared.u64 t, %1; cvt.u32.u64 %0, t; }" : "=r"(a) : "l"(p));
    return a;
}
__device__ __forceinline__ void cp_async16(uint32_t s, const void* g) {
    asm volatile("cp.async.cg.shared.global [%0], [%1], 16;" :: "r"(s), "l"(g));
}
#define CP_COMMIT() asm volatile("cp.async.commit_group;" ::: "memory")
#define CP_WAIT(n)  asm volatile("cp.async.wait_group %0;" :: "n"(n) : "memory")

// fp16 mma: D(f32) += A(f16) B(f16)^T ; A=4 regs (8 halves), B=2 regs (4 halves)
#define MMA16(dd, af, b0, b1) \
    asm volatile("mma.sync.aligned.m16n8k16.row.col.f32.f16.f16.f32 " \
        "{%0,%1,%2,%3}, {%4,%5,%6,%7}, {%8,%9}, {%0,%1,%2,%3};" \
        : "+f"((dd)[0]), "+f"((dd)[1]), "+f"((dd)[2]), "+f"((dd)[3]) \
        : "r"((af)[0]), "r"((af)[1]), "r"((af)[2]), "r"((af)[3]), "r"(b0), "r"(b1))

// ldmatrix x4: each lane supplies the address of one 16B row of an 8x8 b16 tile
#define LDSM4(r0, r1, r2, r3, addr) \
    asm volatile("ldmatrix.sync.aligned.m8n8.x4.shared.b16 {%0,%1,%2,%3}, [%4];" \
        : "=r"(r0), "=r"(r1), "=r"(r2), "=r"(r3) : "r"(addr))

// half-element index in a [row][64-half] tile (128B rows, 16B-chunk XOR swizzle)
__device__ __forceinline__ int swzh(int row, int k) {
    return (row << 6) + ((((k >> 3) ^ row) & 7) << 3) + (k & 7);
}
__device__ __forceinline__ uint32_t ldsu(const __half* p) {
    return *(const uint32_t*)p;
}

// ============================================================
// fp16 mma.sync GEMM: C = scale*(A B^T) (+bias, +Res, ReLU)
// CTA 128 x (NT*16); BK=64 halves; 3-stage cp.async; 128 threads; 2 CTAs/SM.
// ldmatrix.x4 fragment loads. QKV: epilogue routes q/k/vT (fp16).
// TOUT: C is fp16. Ct: fp16 shadow of C.
// ============================================================
template<int NT, bool RELU, bool RES, bool QKV, bool TOUT>
__global__ __launch_bounds__(128, 2) void mma_gemm(
    const __half* __restrict__ A, int lda,
    const __half* __restrict__ B, int ldb,
    void* __restrict__ Cp, int ldc,
    const float* __restrict__ bias, const float* __restrict__ Res,
    float scale, int K,
    __half* __restrict__ Ck, __half* __restrict__ Cv, __half* __restrict__ Ct)
{
    constexpr int BM = 128, BK = 64;
    constexpr int BN = NT * 16;
    constexpr int NSTAGE = 3;
    constexpr int STAGE_H = (BM + BN) * BK;      // halves per stage

    extern __shared__ float smem[];
    float* sbias = smem;
    __half* sdata = (__half*)(smem + BN);

    const int t = threadIdx.x;
    const int m0 = blockIdx.y * BM;
    const int n0 = blockIdx.x * BN;

    if (bias != nullptr && t < BN) sbias[t] = bias[n0 + t];

    auto load_stage = [&](int st, int k0) {
        __half* sa = sdata + (st % NSTAGE) * STAGE_H;
        __half* sb = sa + BM * BK;
        #pragma unroll
        for (int i = 0; i < 8; i++) {             // A: 128 rows x 8 chunks
            int j = t + 128 * i;
            int m = j >> 3, f = j & 7;
            uint32_t dst = su32(&sa[(m << 6) + (((f ^ m) & 7) << 3)]);
            cp_async16(dst, A + (size_t)(m0 + m) * lda + k0 + (f << 3));
        }
        #pragma unroll
        for (int i = 0; i < NT; i++) {            // B: BN rows x 8 chunks
            int j = t + 128 * i;
            int n = j >> 3, f = j & 7;
            uint32_t dst = su32(&sb[(n << 6) + (((f ^ n) & 7) << 3)]);
            cp_async16(dst, B + (size_t)(n0 + n) * ldb + k0 + (f << 3));
        }
        CP_COMMIT();
    };

    const int nst = K / BK;
    load_stage(0, 0);
    load_stage(1, BK);

    const int lane = t & 31, w = t >> 5;
    const int wm = w >> 1, wn = w & 1;
    const int g = lane >> 2, t4 = lane & 3;
    // ldmatrix lane->address constants
    const int jj  = lane >> 3;                   // 0..3 (matrix id)
    const int rA  = ((jj & 1) << 3) + (lane & 7);
    const int kA  = (jj >> 1) << 3;
    const int rB  = lane & 7;
    const int ntO = jj >> 1;                     // which nt of the pair
    const int kB_ = (jj & 1) << 3;

    float d[4][NT][4] = {};

    for (int s = 0; s < nst; s++) {
        if (s < nst - 1) { CP_WAIT(1); } else { CP_WAIT(0); }
        __syncthreads();
        if (s + 2 < nst) load_stage(s + 2, (s + 2) * BK);

        uint32_t sa_u = su32(sdata + (s % NSTAGE) * STAGE_H);
        uint32_t sb_u = sa_u + BM * BK * 2;
        #pragma unroll
        for (int k16 = 0; k16 < 4; k16++) {
            const int kb = k16 << 4;
            uint32_t af[4][4];
            #pragma unroll
            for (int mt = 0; mt < 4; mt++) {
                int r = wm * 64 + mt * 16 + rA;
                LDSM4(af[mt][0], af[mt][1], af[mt][2], af[mt][3],
                      sa_u + (swzh(r, kb + kA) << 1));
            }
            uint32_t bf[NT][2];
            #pragma unroll
            for (int np = 0; np < NT / 2; np++) {
                int n = wn * NT * 8 + ((np * 2 + ntO) << 3) + rB;
                LDSM4(bf[np * 2][0], bf[np * 2][1], bf[np * 2 + 1][0], bf[np * 2 + 1][1],
                      sb_u + (swzh(n, kb + kB_) << 1));
            }
            #pragma unroll
            for (int nt = 0; nt < NT; nt++)
                #pragma unroll
                for (int mt = 0; mt < 4; mt++) MMA16(d[mt][nt], af[mt], bf[nt][0], bf[nt][1]);
        }
    }

    // ---------------- epilogue ----------------
    const int colw = wn * NT * 8;
    #pragma unroll
    for (int mt = 0; mt < 4; mt++) {
        #pragma unroll
        for (int h2 = 0; h2 < 2; h2++) {
            const int m = m0 + wm * 64 + mt * 16 + g + h2 * 8;
            if (QKV) {
                const int region = n0 >> 9;       // 0=Q, 1=K, 2=V
                const int nb = n0 & 511;
                if (region < 2) {
                    __half* crow = (region == 0 ? (__half*)Cp : Ck) + (size_t)m * 512 + nb;
                    #pragma unroll
                    for (int nt = 0; nt < NT; nt++) {
                        int cl = colw + nt * 8 + 2 * t4;
                        float v0 = d[mt][nt][h2 * 2]     + sbias[cl];
                        float v1 = d[mt][nt][h2 * 2 + 1] + sbias[cl + 1];
                        *(__half2*)(crow + cl) = __floats2half2_rn(v0, v1);
                    }
                } else {
                    #pragma unroll
                    for (int nt = 0; nt < NT; nt++) {
                        int cl = colw + nt * 8 + 2 * t4;
                        float v0 = d[mt][nt][h2 * 2]     + sbias[cl];
                        float v1 = d[mt][nt][h2 * 2 + 1] + sbias[cl + 1];
                        int gc = nb + cl;
                        int hh = gc >> 6, e = gc & 63;
                        size_t base = ((size_t)((m >> 9) * Hn + hh) * 64 + e) * 512
                                      + (size_t)(m & 511);
                        Cv[base]       = __float2half_rn(v0);
                        Cv[base + 512] = __float2half_rn(v1);
                    }
                }
            } else if (TOUT) {
                __half* crow = (__half*)Cp + (size_t)m * ldc + n0;
                #pragma unroll
                for (int nt = 0; nt < NT; nt++) {
                    int cl = colw + nt * 8 + 2 * t4;
                    float v0 = d[mt][nt][h2 * 2]     + sbias[cl];
                    float v1 = d[mt][nt][h2 * 2 + 1] + sbias[cl + 1];
                    if (RELU) { v0 = fmaxf(v0, 0.f); v1 = fmaxf(v1, 0.f); }
                    *(__half2*)(crow + cl) = __floats2half2_rn(v0, v1);
                }
            } else {
                float* crow = (float*)Cp + (size_t)m * ldc + n0;
                __half* trow = (Ct != nullptr) ? (Ct + (size_t)m * ldc + n0) : nullptr;
                const float* rrow = RES ? (Res + (size_t)m * ldc + n0) : nullptr;
                #pragma unroll
                for (int nt = 0; nt < NT; nt++) {
                    int cl = colw + nt * 8 + 2 * t4;
                    float v0 = d[mt][nt][h2 * 2]     * scale;
                    float v1 = d[mt][nt][h2 * 2 + 1] * scale;
                    if (bias != nullptr) { v0 += sbias[cl]; v1 += sbias[cl + 1]; }
                    if (RELU) { v0 = fmaxf(v0, 0.f); v1 = fmaxf(v1, 0.f); }
                    if (RES) {
                        float2 r = *(const float2*)(rrow + cl);
                        v0 += r.x; v1 += r.y;
                    }
                    *(float2*)(crow + cl) = make_float2(v0, v1);
                    if (Ct != nullptr)
                        *(__half2*)(trow + cl) = __floats2half2_rn(v0, v1);
                }
            }
        }
    }
}

// ============================================================
// flash attention (fp16 operands, fp32 accum/softmax), ldmatrix frag loads
// per (b,h,qtile 128); 256 threads; smem 96KB.
// ============================================================
#define FLASH_SMEM 98304
#define NEG_INF (-1e30f)

__global__ __launch_bounds__(256) void flash_kernel()
{
    extern __shared__ __half smh[];
    __half* Ps = smh;                          // 16384 halves

    const int t = threadIdx.x;
    const int lane = t & 31, w = t >> 5;
    const int g = lane >> 2, t4 = lane & 3;
    const int jj  = lane >> 3;
    const int rA  = ((jj & 1) << 3) + (lane & 7);
    const int kA  = (jj >> 1) << 3;
    const int rB  = lane & 7;
    const int ntO = jj >> 1;
    const int kB_ = (jj & 1) << 3;
    const int q0 = blockIdx.x * 128;
    const int b = blockIdx.y >> 3, h = blockIdx.y & 7;
    const int r0 = w * 16;

    const __half* qg = g_q  + (size_t)(b * Sn + q0) * Dn + h * HDn;
    const __half* kg = g_k  + (size_t)(b * Sn) * Dn + h * HDn;
    const __half* vg = g_vT + (size_t)(b * Hn + h) * HDn * Sn;

    // ---- stage Q into Ps chunk0: [128 q][64 e] ----
    #pragma unroll
    for (int i = 0; i < 4; i++) {
        int j = t + 256 * i;
        int r = j >> 3, f = j & 7;
        uint32_t dst = su32(&Ps[(r << 6) + (((f ^ r) & 7) << 3)]);
        cp_async16(dst, qg + (size_t)r * Dn + (f << 3));
    }
    CP_COMMIT();

    auto load_kv = [&](int tile, int st) {
        __half* kb = smh + 16384 + st * 16384;
        __half* vb = kb + 8192;
        #pragma unroll
        for (int i = 0; i < 4; i++) {          // K tile [128 s][64 e]
            int j = t + 256 * i;
            int r = j >> 3, f = j & 7;
            uint32_t dst = su32(&kb[(r << 6) + (((f ^ r) & 7) << 3)]);
            cp_async16(dst, kg + (size_t)(tile * 128 + r) * Dn + (f << 3));
        }
        #pragma unroll
        for (int i = 0; i < 4; i++) {          // V^T tile [64 e][128 s] -> 2 chunks
            int j = t + 256 * i;
            int e = j >> 4, f = j & 15;
            int ss = f >> 3, fc = f & 7;
            uint32_t dst = su32(&vb[ss * 4096 + (e << 6) + (((fc ^ e) & 7) << 3)]);
            cp_async16(dst, vg + (size_t)e * Sn + tile * 128 + (f << 3));
        }
        CP_COMMIT();
    };
    load_kv(0, 0);
    load_kv(1, 1);

    // ---- Q fragments (held in regs) ----
    CP_WAIT(2);
    __syncthreads();
    uint32_t qf[4][4];
    {
        uint32_t ps_u = su32(Ps);
        #pragma unroll
        for (int k16 = 0; k16 < 4; k16++) {
            const int kb = k16 << 4;
            LDSM4(qf[k16][0], qf[k16][1], qf[k16][2], qf[k16][3],
                  ps_u + (swzh(r0 + rA, kb + kA) << 1));
        }
    }
    __syncthreads();

    float m0 = NEG_INF, m1 = NEG_INF, l0 = 0.f, l1 = 0.f;
    float o[8][4] = {};
    const uint32_t ps_u = su32(Ps);

    for (int tile = 0; tile < 4; tile++) {
        if (tile < 3) { CP_WAIT(1); } else { CP_WAIT(0); }
        __syncthreads();
        const __half* kbp = smh + 16384 + (tile & 1) * 16384;
        const uint32_t kb_u = su32(kbp);
        const uint32_t vb_u = kb_u + 8192 * 2;

        // ---- S = Q K^T ----
        float s[16][4];
        #pragma unroll
        for (int nt = 0; nt < 16; nt++)
            #pragma unroll
            for (int j = 0; j < 4; j++) s[nt][j] = 0.f;
        #pragma unroll
        for (int k16 = 0; k16 < 4; k16++) {
            const int kk = k16 << 4;
            #pragma unroll
            for (int np = 0; np < 8; np++) {
                uint32_t b00, b01, b10, b11;
                int n = ((np * 2 + ntO) << 3) + rB;
                LDSM4(b00, b01, b10, b11, kb_u + (swzh(n, kk + kB_) << 1));
                MMA16(s[np * 2],     qf[k16], b00, b01);
                MMA16(s[np * 2 + 1], qf[k16], b10, b11);
            }
        }

        // ---- online softmax update ----
        float rm0 = NEG_INF, rm1 = NEG_INF;
        #pragma unroll
        for (int nt = 0; nt < 16; nt++) {
            s[nt][0] *= 0.125f; s[nt][1] *= 0.125f;
            s[nt][2] *= 0.125f; s[nt][3] *= 0.125f;
            rm0 = fmaxf(rm0, fmaxf(s[nt][0], s[nt][1]));
            rm1 = fmaxf(rm1, fmaxf(s[nt][2], s[nt][3]));
        }
        rm0 = fmaxf(rm0, __shfl_xor_sync(0xFFFFFFFF, rm0, 1));
        rm0 = fmaxf(rm0, __shfl_xor_sync(0xFFFFFFFF, rm0, 2));
        rm1 = fmaxf(rm1, __shfl_xor_sync(0xFFFFFFFF, rm1, 1));
        rm1 = fmaxf(rm1, __shfl_xor_sync(0xFFFFFFFF, rm1, 2));
        float mn0 = fmaxf(m0, rm0), mn1 = fmaxf(m1, rm1);
        float a0 = __expf(m0 - mn0), a1 = __expf(m1 - mn1);
        m0 = mn0; m1 = mn1;

        float rs0 = 0.f, rs1 = 0.f;
        #pragma unroll
        for (int nt = 0; nt < 16; nt++) {
            float p0 = __expf(s[nt][0] - m0);
            float p1 = __expf(s[nt][1] - m0);
            float p2 = __expf(s[nt][2] - m1);
            float p3 = __expf(s[nt][3] - m1);
            rs0 += p0 + p1; rs1 += p2 + p3;
            int col = nt * 8 + 2 * t4;
            int ch = col >> 6, kc = col & 63;
            *(__half2*)&Ps[ch * 8192 + swzh(r0 + g, kc)]     = __floats2half2_rn(p0, p1);
            *(__half2*)&Ps[ch * 8192 + swzh(r0 + g + 8, kc)] = __floats2half2_rn(p2, p3);
        }
        rs0 += __shfl_xor_sync(0xFFFFFFFF, rs0, 1);
        rs0 += __shfl_xor_sync(0xFFFFFFFF, rs0, 2);
        rs1 += __shfl_xor_sync(0xFFFFFFFF, rs1, 1);
        rs1 += __shfl_xor_sync(0xFFFFFFFF, rs1, 2);
        l0 = l0 * a0 + rs0;
        l1 = l1 * a1 + rs1;
        #pragma unroll
        for (int nt = 0; nt < 8; nt++) {
            o[nt][0] *= a0; o[nt][1] *= a0;
            o[nt][2] *= a1; o[nt][3] *= a1;
        }
        __syncwarp();

        // ---- O += P @ V^T ----
        #pragma unroll
        for (int ks = 0; ks < 8; ks++) {
            const int ch = ks >> 2, kk = (ks << 4) & 63;
            uint32_t af[4];
            LDSM4(af[0], af[1], af[2], af[3],
                  ps_u + ch * 16384 + (swzh(r0 + rA, kk + kA) << 1));
            #pragma unroll
            for (int np = 0; np < 4; np++) {
                uint32_t b00, b01, b10, b11;
                int n = ((np * 2 + ntO) << 3) + rB;
                LDSM4(b00, b01, b10, b11, vb_u + ch * 8192 + (swzh(n, kk + kB_) << 1));
                MMA16(o[np * 2],     af, b00, b01);
                MMA16(o[np * 2 + 1], af, b10, b11);
            }
        }
        __syncthreads();
        if (tile + 2 < 4) load_kv(tile + 2, tile & 1);
    }

    // ---- epilogue: O / l -> g_att (fp16) ----
    float inv0 = 1.0f / l0, inv1 = 1.0f / l1;
    __half* orow0 = g_att + (size_t)(b * Sn + q0 + r0 + g) * Dn + h * HDn;
    __half* orow1 = orow0 + 8 * Dn;
    #pragma unroll
    for (int nt = 0; nt < 8; nt++) {
        int col = nt * 8 + 2 * t4;
        *(__half2*)(orow0 + col) = __floats2half2_rn(o[nt][0] * inv0, o[nt][1] * inv0);
        *(__half2*)(orow1 + col) = __floats2half2_rn(o[nt][2] * inv1, o[nt][3] * inv1);
    }
}

// ============================================================
// weight transpose -> fp16: dst[zdst + c*R + r] = h(src[z][r][c])
// ============================================================
__global__ void transpose_kernel(const float* __restrict__ src, __half* __restrict__ dst,
                                 int R, int C, size_t zstride, size_t doff)
{
    __shared__ float tile[32][33];
    size_t zsrc = (size_t)blockIdx.z * R * C;
    size_t zdst = (size_t)blockIdx.z * zstride + doff;
    int c0 = blockIdx.x * 32, r0 = blockIdx.y * 32;
    int tx = threadIdx.x, ty = threadIdx.y;       // 32 x 8
    #pragma unroll
    for (int j = 0; j < 32; j += 8)
        tile[ty + j][tx] = src[zsrc + (size_t)(r0 + ty + j) * C + c0 + tx];
    __syncthreads();
    #pragma unroll
    for (int j = 0; j < 32; j += 8)
        dst[zdst + (size_t)(c0 + ty + j) * R + r0 + tx] = __float2half_rn(tile[tx][ty + j]);
}

__global__ void packbias_kernel(const float* __restrict__ bq, const float* __restrict__ bk,
                                const float* __restrict__ bv, float* __restrict__ dst)
{
    int i = blockIdx.x, t = threadIdx.x;   // Ln x 512
    dst[i * 1536 + t]        = bq[i * 512 + t];
    dst[i * 1536 + 512 + t]  = bk[i * 512 + t];
    dst[i * 1536 + 1024 + t] = bv[i * 512 + t];
}

// ============================================================
// build x = class_proj(concat(embed[idx], nd)); writes fp32 + fp16 shadow
// ============================================================
__global__ void build_x_kernel(const float* __restrict__ sol,
                               const float* __restrict__ cap,
                               const float* __restrict__ emb,
                               const float* __restrict__ srcW, const float* __restrict__ srcB,
                               const float* __restrict__ candW, const float* __restrict__ candB,
                               const float* __restrict__ depW, const float* __restrict__ depB)
{
    int row = blockIdx.x;
    int b = row / Sn, s = row % Sn;
    __shared__ float xin[INDIM];
    int t = threadIdx.x;

    int idx = (int)sol[(size_t)row * 4 + 0];
    xin[t] = emb[(size_t)idx * Cn + t];
    if (t == 0) {
        float rem = sol[(size_t)(b * Sn) * 4 + 3];
        float nd = (s == 0) ? 0.0f : 2.0f * (sol[(size_t)row * 4 + 2] - rem) / cap[b];
        xin[Cn] = nd;
    }
    __syncthreads();

    const float* W; const float* bb;
    if (s == 0)           { W = srcW;  bb = srcB;  }
    else if (s == Sn - 1) { W = depW;  bb = depB;  }
    else                  { W = candW; bb = candB; }

    int c = t;
    float acc0 = bb[c], acc1 = bb[c + 256];
    #pragma unroll 4
    for (int k = 0; k < INDIM; k++) {
        float xv = xin[k];
        acc0 += xv * W[k * Dn + c];
        acc1 += xv * W[k * Dn + c + 256];
    }
    g_x [(size_t)row * Dn + c]       = acc0;
    g_x [(size_t)row * Dn + c + 256] = acc1;
    g_xt[(size_t)row * Dn + c]       = __float2half_rn(acc0);
    g_xt[(size_t)row * Dn + c + 256] = __float2half_rn(acc1);
}

// ============================================================
// feasibility head
// ============================================================
__global__ void feas_kernel(const float* __restrict__ fW,
                            const float* __restrict__ fB,
                            float* __restrict__ out)
{
    int s = blockIdx.x + 1;
    int b = blockIdx.y;
    const float* xr = g_x + (size_t)(b * Sn + s) * Dn;
    int t = threadIdx.x;
    float acc = 0.f;
    #pragma unroll 4
    for (int k = t; k < Dn; k += 128) acc += xr[k] * fW[k];
    __shared__ float red[128];
    red[t] = acc; __syncthreads();
    for (int o = 64; o > 0; o >>= 1) {
        if (t < o) red[t] += red[t + o];
        __syncthreads();
    }
    if (t == 0) out[OUT_FEAS_OFF + b * 510 + (s - 1)] = red[0] + fB[0];
}

// ============================================================
// pointer logits
// ============================================================
__global__ void logits_kernel(const float* __restrict__ pW,
                              const float* __restrict__ pB,
                              float* __restrict__ out)
{
    int s = blockIdx.x + 1;
    int b = blockIdx.y;
    const float* xr = g_x + (size_t)(b * Sn + s) * Dn;
    int t = threadIdx.x;
    float a0 = 0.f, a1 = 0.f;
    #pragma unroll 4
    for (int k = t; k < Dn; k += 128) {
        float xv = xr[k];
        a0 += xv * pW[k * 2 + 0];
        a1 += xv * pW[k * 2 + 1];
    }
    __shared__ float r0[128], r1[128];
    r0[t] = a0; r1[t] = a1; __syncthreads();
    for (int o = 64; o > 0; o >>= 1) {
        if (t < o) { r0[t] += r0[t + o]; r1[t] += r1[t + o]; }
        __syncthreads();
    }
    if (t == 0) {
        out[b * OUT_LOGITS_PER_B + (s - 1)]       = r0[0] + pB[0];
        out[b * OUT_LOGITS_PER_B + 510 + (s - 1)] = r1[0] + pB[1];
    }
}

// ============================================================
// host orchestration
// ============================================================
extern "C" void kernel_launch(void* const* d_in, const int* in_sizes, int n_in,
                              void* d_out, int out_size)
{
    const float* sol   = (const float*)d_in[0];
    const float* cap   = (const float*)d_in[1];
    const float* emb   = (const float*)d_in[2];
    const float* srcW  = (const float*)d_in[3];
    const float* srcB  = (const float*)d_in[4];
    const float* candW = (const float*)d_in[5];
    const float* candB = (const float*)d_in[6];
    const float* depW  = (const float*)d_in[7];
    const float* depB  = (const float*)d_in[8];
    const float* feasW = (const float*)d_in[9];
    const float* feasB = (const float*)d_in[10];
    const float* Wq    = (const float*)d_in[11];
    const float* bq    = (const float*)d_in[12];
    const float* Wk    = (const float*)d_in[13];
    const float* bk    = (const float*)d_in[14];
    const float* Wv    = (const float*)d_in[15];
    const float* bv    = (const float*)d_in[16];
    const float* Wo    = (const float*)d_in[17];
    const float* bo    = (const float*)d_in[18];
    // d_in[19] = s_scale : softmax-shift-invariant, unused
    const float* W1    = (const float*)d_in[20];
    const float* b1    = (const float*)d_in[21];
    const float* W2    = (const float*)d_in[22];
    const float* b2    = (const float*)d_in[23];
    const float* ptrW  = (const float*)d_in[24];
    const float* ptrB  = (const float*)d_in[25];
    float* out = (float*)d_out;
    (void)in_sizes; (void)n_in; (void)out_size;

    float  *px;
    __half *pxt, *pq, *pk, *patt, *pvT, *ph;
    __half *pwqkvT, *pwoT, *pw1T, *pw2T;
    float  *pbqkv;
    cudaGetSymbolAddress((void**)&px,     g_x);
    cudaGetSymbolAddress((void**)&pxt,    g_xt);
    cudaGetSymbolAddress((void**)&pq,     g_q);
    cudaGetSymbolAddress((void**)&pk,     g_k);
    cudaGetSymbolAddress((void**)&patt,   g_att);
    cudaGetSymbolAddress((void**)&pvT,    g_vT);
    cudaGetSymbolAddress((void**)&ph,     g_h);
    cudaGetSymbolAddress((void**)&pwqkvT, g_wqkvT);
    cudaGetSymbolAddress((void**)&pbqkv,  g_bqkv);
    cudaGetSymbolAddress((void**)&pwoT,   g_woT);
    cudaGetSymbolAddress((void**)&pw1T,   g_w1T);
    cudaGetSymbolAddress((void**)&pw2T,   g_w2T);

    const int SM8 = 128 * 4 + 3 * (128 + 128) * 64 * 2;   // 98816
    const int SM4 = 64 * 4 + 3 * (128 + 64) * 64 * 2;     // 73984
    cudaFuncSetAttribute(mma_gemm<8, false, false, true,  false>, cudaFuncAttributeMaxDynamicSharedMemorySize, SM8);
    cudaFuncSetAttribute(mma_gemm<8, true,  false, false, true >, cudaFuncAttributeMaxDynamicSharedMemorySize, SM8);
    cudaFuncSetAttribute(mma_gemm<4, false, true,  false, false>, cudaFuncAttributeMaxDynamicSharedMemorySize, SM4);
    cudaFuncSetAttribute(flash_kernel, cudaFuncAttributeMaxDynamicSharedMemorySize, FLASH_SMEM);

    const size_t DD = (size_t)Dn * Dn;           // 262144
    const size_t DH = (size_t)Dn * HIDn;         // 1048576
    const size_t QKVS = (size_t)1536 * Dn;       // 786432

    // ---- pack weights (fp16): QKV concat [1536,512], others [N,K] ----
    dim3 tb(32, 8);
    transpose_kernel<<<dim3(16, 16, Ln), tb>>>(Wq, pwqkvT, Dn, Dn, QKVS, 0);
    transpose_kernel<<<dim3(16, 16, Ln), tb>>>(Wk, pwqkvT, Dn, Dn, QKVS, DD);
    transpose_kernel<<<dim3(16, 16, Ln), tb>>>(Wv, pwqkvT, Dn, Dn, QKVS, 2 * DD);
    transpose_kernel<<<dim3(16, 16, Ln), tb>>>(Wo, pwoT, Dn, Dn, DD, 0);
    transpose_kernel<<<dim3(64, 16, Ln), tb>>>(W1, pw1T, Dn, HIDn, DH, 0);
    transpose_kernel<<<dim3(16, 64, Ln), tb>>>(W2, pw2T, HIDn, Dn, DH, 0);
    packbias_kernel<<<Ln, 512>>>(bq, bk, bv, pbqkv);

    build_x_kernel<<<Mn, 256>>>(sol, cap, emb, srcW, srcB, candW, candB, depW, depB);

    const dim3 gQKV(12, 32, 1);     // 384 CTAs (BN=128)
    const dim3 gP4 (8, 32, 1);      // 256 CTAs (BN=64)
    const dim3 gFF1(16, 32, 1);     // 512 CTAs
    const dim3 gFl (4, 64, 1);      // 256 CTAs

    for (int i = 0; i < Ln; i++) {
        // ---- fused QKV projection (fp16 outputs; V per-head-transposed) ----
        mma_gemm<8, false, false, true, false><<<gQKV, 128, SM8>>>(
            pxt, Dn,  pwqkvT + i * QKVS, Dn,  pq, Dn,
            pbqkv + i * 1536, nullptr, 1.0f, Dn, pk, pvT, nullptr);

        // ---- flash attention ----
        flash_kernel<<<gFl, 256, FLASH_SMEM>>>();

        // ---- O projection + residual (writes x fp32 + xt fp16) ----
        mma_gemm<4, false, true, false, false><<<gP4, 128, SM4>>>(
            patt, Dn,  pwoT + i * DD, Dn,  px, Dn,
            bo + i * Dn, px, 1.0f, Dn, nullptr, nullptr, pxt);

        if (i == 0)
            feas_kernel<<<dim3(510, Bn), 128>>>(feasW, feasB, out);

        // ---- FFN (h stored fp16) ----
        mma_gemm<8, true, false, false, true><<<gFF1, 128, SM8>>>(
            pxt, Dn,  pw1T + i * DH, Dn,  ph, HIDn,
            b1 + i * HIDn, nullptr, 1.0f, Dn, nullptr, nullptr, nullptr);
        mma_gemm<4, false, true, false, false><<<gP4, 128, SM4>>>(
            ph, HIDn,  pw2T + i * DH, HIDn,  px, Dn,
            b2 + i * Dn, px, 1.0f, HIDn, nullptr, nullptr, pxt);
    }

    logits_kernel<<<dim3(510, Bn), 128>>>(ptrW, ptrB, out);
}